// round 1
// baseline (speedup 1.0000x reference)
#include <cuda_runtime.h>
#include <math.h>

// Problem constants (fixed by the dataset)
#define NTOK  4096
#define HDIM  512
#define CCH   128      // children per category (log_odds outputs)
#define KCAT  64       // categories
#define MCI   4        // LSTM cells
#define INDIM 1024     // E + H (LSTMCell input width)
#define GDIM  2048     // 4*H gates
#define FDIM  1536     // INDIM + HDIM (concat input for gates GEMM)

// ---- device scratch (static: no allocation allowed) ----
__device__ float g_gates[(size_t)NTOK * GDIM];     // 33.5 MB gate scratch
__device__ int   g_perm_ci[NTOK];
__device__ int   g_perm_cat[NTOK];
__device__ int   g_off_ci[MCI + 1];
__device__ int   g_off_cat[KCAT + 1];
__device__ int   g_pos_ci[MCI];
__device__ int   g_pos_cat[KCAT];
__device__ int   g_cnt_ci[MCI];
__device__ int   g_cnt_cat[KCAT];

// ---------------- counting sort (token -> bucket) ----------------
__global__ void k_zero() {
    int t = threadIdx.x;
    if (t < MCI)  g_cnt_ci[t]  = 0;
    if (t < KCAT) g_cnt_cat[t] = 0;
}

__global__ void k_hist(const int* __restrict__ cat, const int* __restrict__ ci) {
    int n = blockIdx.x * blockDim.x + threadIdx.x;
    if (n < NTOK) {
        atomicAdd(&g_cnt_ci[ci[n]], 1);
        atomicAdd(&g_cnt_cat[cat[n]], 1);
    }
}

__global__ void k_scan() {
    if (threadIdx.x == 0) {
        int s = 0;
        for (int i = 0; i < MCI; i++) { g_off_ci[i] = s; g_pos_ci[i] = s; s += g_cnt_ci[i]; }
        g_off_ci[MCI] = s;
        s = 0;
        for (int i = 0; i < KCAT; i++) { g_off_cat[i] = s; g_pos_cat[i] = s; s += g_cnt_cat[i]; }
        g_off_cat[KCAT] = s;
    }
}

__global__ void k_scatter(const int* __restrict__ cat, const int* __restrict__ ci) {
    int n = blockIdx.x * blockDim.x + threadIdx.x;
    if (n < NTOK) {
        int p = atomicAdd(&g_pos_ci[ci[n]], 1);
        g_perm_ci[p] = n;
        int q = atomicAdd(&g_pos_cat[cat[n]], 1);
        g_perm_cat[q] = n;
    }
}

// ---------------- gates GEMM: per ci-bucket, gates[t,g] = [x|h] . W[k][g,:] ----------------
// Tiles: BM=64 tokens, BN=64 gate outputs, BK=16. 256 threads, 4x4 micro-tile.
__global__ __launch_bounds__(256) void gates_gemm(
    const float* __restrict__ x, const float* __restrict__ h,
    const float* __restrict__ W_ih, const float* __restrict__ W_hh,
    const float* __restrict__ b_ih, const float* __restrict__ b_hh)
{
    const int k   = blockIdx.z;
    const int beg = g_off_ci[k];
    const int cnt = g_off_ci[k + 1] - beg;
    const int m0  = blockIdx.x * 64;
    if (m0 >= cnt) return;
    const int n0  = blockIdx.y * 64;

    __shared__ float As[16][68];   // [kk][token], pad 4 -> 16B-aligned rows
    __shared__ float Bs[16][68];   // [kk][gate]

    const int tid = threadIdx.x;
    const int tx  = tid & 15;      // output dir
    const int ty  = tid >> 4;      // token dir
    const int lr  = tid >> 2;      // 0..63 load row
    const int lc  = (tid & 3) * 4; // 0,4,8,12 load col group

    int tA = -1;
    if (m0 + lr < cnt) tA = g_perm_ci[beg + m0 + lr];
    const size_t wrow_ih = ((size_t)k * GDIM + (n0 + lr)) * INDIM;
    const size_t wrow_hh = ((size_t)k * GDIM + (n0 + lr)) * HDIM;

    float acc[4][4];
#pragma unroll
    for (int i = 0; i < 4; i++)
#pragma unroll
        for (int j = 0; j < 4; j++) acc[i][j] = 0.f;

    for (int ib = 0; ib < FDIM; ib += 16) {
        const int ii = ib + lc;
        float4 va = make_float4(0.f, 0.f, 0.f, 0.f);
        if (tA >= 0) {
            va = (ii < INDIM)
               ? *(const float4*)(x + (size_t)tA * INDIM + ii)
               : *(const float4*)(h + (size_t)tA * HDIM + (ii - INDIM));
        }
        float4 vb = (ii < INDIM)
               ? *(const float4*)(W_ih + wrow_ih + ii)
               : *(const float4*)(W_hh + wrow_hh + (ii - INDIM));

        As[lc + 0][lr] = va.x; As[lc + 1][lr] = va.y;
        As[lc + 2][lr] = va.z; As[lc + 3][lr] = va.w;
        Bs[lc + 0][lr] = vb.x; Bs[lc + 1][lr] = vb.y;
        Bs[lc + 2][lr] = vb.z; Bs[lc + 3][lr] = vb.w;
        __syncthreads();

#pragma unroll
        for (int kk = 0; kk < 16; kk++) {
            float4 a4 = *(const float4*)&As[kk][ty * 4];
            float4 b4 = *(const float4*)&Bs[kk][tx * 4];
            float a[4] = {a4.x, a4.y, a4.z, a4.w};
            float b[4] = {b4.x, b4.y, b4.z, b4.w};
#pragma unroll
            for (int i = 0; i < 4; i++)
#pragma unroll
                for (int j = 0; j < 4; j++)
                    acc[i][j] = fmaf(a[i], b[j], acc[i][j]);
        }
        __syncthreads();
    }

#pragma unroll
    for (int i = 0; i < 4; i++) {
        int m = m0 + ty * 4 + i;
        if (m < cnt) {
            int t = g_perm_ci[beg + m];
#pragma unroll
            for (int j = 0; j < 4; j++) {
                int g = n0 + tx * 4 + j;
                g_gates[(size_t)t * GDIM + g] =
                    acc[i][j] + b_ih[k * GDIM + g] + b_hh[k * GDIM + g];
            }
        }
    }
}

// ---------------- log_odds GEMM: per cat-bucket, out[t,cch] = et . W_lin[cat][cch,:] ----------------
__global__ __launch_bounds__(256) void logodds_gemm(
    const float* __restrict__ et,
    const float* __restrict__ W_lin, const float* __restrict__ b_lin,
    float* __restrict__ out)
{
    const int kc  = blockIdx.z;
    const int beg = g_off_cat[kc];
    const int cnt = g_off_cat[kc + 1] - beg;
    const int m0  = blockIdx.x * 64;
    if (m0 >= cnt) return;
    const int n0  = blockIdx.y * 64;

    __shared__ float As[16][68];
    __shared__ float Bs[16][68];

    const int tid = threadIdx.x;
    const int tx  = tid & 15;
    const int ty  = tid >> 4;
    const int lr  = tid >> 2;
    const int lc  = (tid & 3) * 4;

    int tA = -1;
    if (m0 + lr < cnt) tA = g_perm_cat[beg + m0 + lr];
    const size_t wrow = ((size_t)kc * CCH + (n0 + lr)) * HDIM;

    float acc[4][4];
#pragma unroll
    for (int i = 0; i < 4; i++)
#pragma unroll
        for (int j = 0; j < 4; j++) acc[i][j] = 0.f;

    for (int ib = 0; ib < HDIM; ib += 16) {
        const int ii = ib + lc;
        float4 va = make_float4(0.f, 0.f, 0.f, 0.f);
        if (tA >= 0) va = *(const float4*)(et + (size_t)tA * HDIM + ii);
        float4 vb = *(const float4*)(W_lin + wrow + ii);

        As[lc + 0][lr] = va.x; As[lc + 1][lr] = va.y;
        As[lc + 2][lr] = va.z; As[lc + 3][lr] = va.w;
        Bs[lc + 0][lr] = vb.x; Bs[lc + 1][lr] = vb.y;
        Bs[lc + 2][lr] = vb.z; Bs[lc + 3][lr] = vb.w;
        __syncthreads();

#pragma unroll
        for (int kk = 0; kk < 16; kk++) {
            float4 a4 = *(const float4*)&As[kk][ty * 4];
            float4 b4 = *(const float4*)&Bs[kk][tx * 4];
            float a[4] = {a4.x, a4.y, a4.z, a4.w};
            float b[4] = {b4.x, b4.y, b4.z, b4.w};
#pragma unroll
            for (int i = 0; i < 4; i++)
#pragma unroll
                for (int j = 0; j < 4; j++)
                    acc[i][j] = fmaf(a[i], b[j], acc[i][j]);
        }
        __syncthreads();
    }

#pragma unroll
    for (int i = 0; i < 4; i++) {
        int m = m0 + ty * 4 + i;
        if (m < cnt) {
            int t = g_perm_cat[beg + m];
#pragma unroll
            for (int j = 0; j < 4; j++) {
                int g = n0 + tx * 4 + j;
                out[(size_t)t * CCH + g] = acc[i][j] + b_lin[kc * CCH + g];
            }
        }
    }
}

// ---------------- LSTM pointwise epilogue ----------------
__device__ __forceinline__ float sigmoidf_(float v) { return 1.f / (1.f + expf(-v)); }

__global__ void lstm_ew(const float* __restrict__ c, float* __restrict__ out) {
    const int idx = blockIdx.x * blockDim.x + threadIdx.x;
    if (idx >= NTOK * HDIM) return;
    const int n = idx / HDIM;
    const int j = idx - n * HDIM;
    const float* G = g_gates + (size_t)n * GDIM;
    float i_ = G[j];
    float f_ = G[HDIM + j];
    float g_ = G[2 * HDIM + j];
    float o_ = G[3 * HDIM + j];
    float c2 = sigmoidf_(f_) * c[idx] + sigmoidf_(i_) * tanhf(g_);
    float h2 = sigmoidf_(o_) * tanhf(c2);
    const size_t OFF_H = (size_t)NTOK * CCH;
    const size_t OFF_C = OFF_H + (size_t)NTOK * HDIM;
    out[OFF_H + idx] = h2;
    out[OFF_C + idx] = c2;
}

// ---------------- launch ----------------
extern "C" void kernel_launch(void* const* d_in, const int* in_sizes, int n_in,
                              void* d_out, int out_size) {
    const float* et    = (const float*)d_in[0];
    const float* x     = (const float*)d_in[1];
    const float* h     = (const float*)d_in[2];
    const float* c     = (const float*)d_in[3];
    const int*   cat   = (const int*)d_in[4];
    const int*   ci    = (const int*)d_in[5];
    const float* W_lin = (const float*)d_in[6];
    const float* b_lin = (const float*)d_in[7];
    const float* W_ih  = (const float*)d_in[8];
    const float* W_hh  = (const float*)d_in[9];
    const float* b_ih  = (const float*)d_in[10];
    const float* b_hh  = (const float*)d_in[11];
    float* out = (float*)d_out;

    k_zero<<<1, 64>>>();
    k_hist<<<NTOK / 256, 256>>>(cat, ci);
    k_scan<<<1, 1>>>();
    k_scatter<<<NTOK / 256, 256>>>(cat, ci);

    // log_odds: grid (token tiles, C/64, K)
    logodds_gemm<<<dim3(NTOK / 64, CCH / 64, KCAT), 256>>>(et, W_lin, b_lin, out);
    // gates: grid (token tiles, 4H/64, M)
    gates_gemm<<<dim3(NTOK / 64, GDIM / 64, MCI), 256>>>(x, h, W_ih, W_hh, b_ih, b_hh);
    // LSTM nonlinearity + output write
    lstm_ew<<<(NTOK * HDIM + 255) / 256, 256>>>(c, out);
}

// round 8
// speedup vs baseline: 2.0987x; 2.0987x over previous
#include <cuda_runtime.h>
#include <cuda_bf16.h>
#include <math.h>
#include <stdint.h>

// Problem constants
#define NTOK  4096
#define HDIM  512
#define CCH   128
#define KCAT  64
#define MCI   4
#define INDIM 1024
#define GDIM  2048      // 4*H
#define FDIM  1536      // INDIM + HDIM
#define APAD  4224      // NTOK + 128 tile slack

// gates GEMM tiling
#define BM 128
#define BN 128
#define BK 32
#define NSTAGES (FDIM / BK)     // 48
#define ROWB 80                 // padded row bytes (32 bf16 = 64B data + 16B pad)
#define MATB (BM * ROWB)        // 10240 bytes per matrix tile
#define STGB (4 * MATB)         // Ahi,Alo,Bhi,Blo
#define SM_BIAS 512
#define SM_STG  1024
#define SM_TOTAL (SM_STG + 2 * STGB)   // 82944
#define EPW 136                 // epilogue f32 row stride (floats)

// ---------------- device scratch (static) ----------------
__device__ __nv_bfloat16 g_Ahi[(size_t)APAD * FDIM];
__device__ __nv_bfloat16 g_Alo[(size_t)APAD * FDIM];
__device__ __nv_bfloat16 g_Whi[(size_t)MCI * GDIM * FDIM];
__device__ __nv_bfloat16 g_Wlo[(size_t)MCI * GDIM * FDIM];
__device__ int g_perm_ci[NTOK];
__device__ int g_perm_cat[NTOK];
__device__ int g_off_ci[MCI + 1];
__device__ int g_off_cat[KCAT + 1];
__device__ int g_pos_ci[MCI];
__device__ int g_pos_cat[KCAT];
__device__ int g_cnt_ci[MCI];
__device__ int g_cnt_cat[KCAT];

// ---------------- PTX helpers (sm_80-level only; NOTHING arch-'a'-gated) ----------------
__device__ __forceinline__ uint32_t smem_u32(const void* p) {
    uint32_t a;
    asm("{ .reg .u64 t; cvta.to.shared.u64 t, %1; cvt.u32.u64 %0, t; }" : "=r"(a) : "l"(p));
    return a;
}
__device__ __forceinline__ void cpa16(uint32_t dst, const void* src) {
    asm volatile("cp.async.cg.shared.global [%0], [%1], 16;" :: "r"(dst), "l"(src));
}
#define CP_COMMIT() asm volatile("cp.async.commit_group;" ::: "memory")
template <int N> __device__ __forceinline__ void cp_wait() {
    asm volatile("cp.async.wait_group %0;" :: "n"(N) : "memory");
}
__device__ __forceinline__ void ldm4(uint32_t* r, uint32_t addr) {
    asm volatile("ldmatrix.sync.aligned.m8n8.x4.shared.b16 {%0,%1,%2,%3}, [%4];"
        : "=r"(r[0]), "=r"(r[1]), "=r"(r[2]), "=r"(r[3]) : "r"(addr));
}
__device__ __forceinline__ void mma16816(float* c, const uint32_t* a, uint32_t b0, uint32_t b1) {
    asm volatile(
        "mma.sync.aligned.m16n8k16.row.col.f32.bf16.bf16.f32 "
        "{%0,%1,%2,%3}, {%4,%5,%6,%7}, {%8,%9}, {%0,%1,%2,%3};"
        : "+f"(c[0]), "+f"(c[1]), "+f"(c[2]), "+f"(c[3])
        : "r"(a[0]), "r"(a[1]), "r"(a[2]), "r"(a[3]), "r"(b0), "r"(b1));
}

// ---------------- counting sort ----------------
__global__ void k_zero() {
    int t = threadIdx.x;
    if (t < MCI)  g_cnt_ci[t]  = 0;
    if (t < KCAT) g_cnt_cat[t] = 0;
}
__global__ void k_hist(const int* __restrict__ cat, const int* __restrict__ ci) {
    int n = blockIdx.x * blockDim.x + threadIdx.x;
    if (n < NTOK) {
        atomicAdd(&g_cnt_ci[ci[n]], 1);
        atomicAdd(&g_cnt_cat[cat[n]], 1);
    }
}
__global__ void k_scan() {
    if (threadIdx.x == 0) {
        int s = 0;
        for (int i = 0; i < MCI; i++) { g_off_ci[i] = s; g_pos_ci[i] = s; s += g_cnt_ci[i]; }
        g_off_ci[MCI] = s;
        s = 0;
        for (int i = 0; i < KCAT; i++) { g_off_cat[i] = s; g_pos_cat[i] = s; s += g_cnt_cat[i]; }
        g_off_cat[KCAT] = s;
    }
}
__global__ void k_scatter(const int* __restrict__ cat, const int* __restrict__ ci) {
    int n = blockIdx.x * blockDim.x + threadIdx.x;
    if (n < NTOK) {
        int p = atomicAdd(&g_pos_ci[ci[n]], 1);
        g_perm_ci[p] = n;
        int q = atomicAdd(&g_pos_cat[cat[n]], 1);
        g_perm_cat[q] = n;
    }
}

// ---------------- pack activations: A_perm[p] = bf16 hi/lo of [x|h][perm[p]] ----------------
__global__ __launch_bounds__(128) void pack_A(const float* __restrict__ x,
                                              const float* __restrict__ h) {
    const int p = blockIdx.x;
    const int t = g_perm_ci[p];
    const int tid = threadIdx.x;
#pragma unroll
    for (int r = 0; r < 3; r++) {
        int col = (tid + 128 * r) * 4;
        float4 v = (col < INDIM)
                 ? *(const float4*)(x + (size_t)t * INDIM + col)
                 : *(const float4*)(h + (size_t)t * HDIM + (col - INDIM));
        float vv[4] = {v.x, v.y, v.z, v.w};
        ushort4 hi, lo;
        unsigned short* hp = &hi.x;
        unsigned short* lp = &lo.x;
#pragma unroll
        for (int j = 0; j < 4; j++) {
            __nv_bfloat16 hb = __float2bfloat16(vv[j]);
            __nv_bfloat16 lb = __float2bfloat16(vv[j] - __bfloat162float(hb));
            hp[j] = __bfloat16_as_ushort(hb);
            lp[j] = __bfloat16_as_ushort(lb);
        }
        *(ushort4*)(g_Ahi + (size_t)p * FDIM + col) = hi;
        *(ushort4*)(g_Alo + (size_t)p * FDIM + col) = lo;
    }
}

// ---------------- pack weights: row R = k*2048 + 4*u + gate -> orig g = gate*512 + u ----------------
__global__ __launch_bounds__(128) void pack_W(const float* __restrict__ W_ih,
                                              const float* __restrict__ W_hh) {
    const int R = blockIdx.x;            // 0..8191
    const int k = R >> 11;
    const int r = R & 2047;
    const int u = r >> 2;
    const int gate = r & 3;
    const int g = gate * 512 + u;
    const int tid = threadIdx.x;
    const float* src_ih = W_ih + ((size_t)k * GDIM + g) * INDIM;
    const float* src_hh = W_hh + ((size_t)k * GDIM + g) * HDIM;
#pragma unroll
    for (int rr = 0; rr < 3; rr++) {
        int col = (tid + 128 * rr) * 4;
        float4 v = (col < INDIM) ? *(const float4*)(src_ih + col)
                                 : *(const float4*)(src_hh + (col - INDIM));
        float vv[4] = {v.x, v.y, v.z, v.w};
        ushort4 hi, lo;
        unsigned short* hp = &hi.x;
        unsigned short* lp = &lo.x;
#pragma unroll
        for (int j = 0; j < 4; j++) {
            __nv_bfloat16 hb = __float2bfloat16(vv[j]);
            __nv_bfloat16 lb = __float2bfloat16(vv[j] - __bfloat162float(hb));
            hp[j] = __bfloat16_as_ushort(hb);
            lp[j] = __bfloat16_as_ushort(lb);
        }
        *(ushort4*)(g_Whi + (size_t)R * FDIM + col) = hi;
        *(ushort4*)(g_Wlo + (size_t)R * FDIM + col) = lo;
    }
}

// ---------------- gates HMMA GEMM + fused LSTM epilogue ----------------
__device__ __forceinline__ void load_stage(int tid, uint32_t sb, int b,
                                           int arow0, int brow0, int ccol) {
#pragma unroll
    for (int i = 0; i < 8; i++) {
        int cidx = tid + 256 * i;        // 0..2047
        int mat  = cidx >> 9;            // 0=Ahi 1=Alo 2=Bhi 3=Blo
        int cc   = cidx & 511;
        int row  = cc >> 2;
        int c16  = cc & 3;
        uint32_t dst = sb + SM_STG + b * STGB + mat * MATB + row * ROWB + c16 * 16;
        const __nv_bfloat16* src;
        if (mat == 0)      src = g_Ahi + (size_t)(arow0 + row) * FDIM + ccol + c16 * 8;
        else if (mat == 1) src = g_Alo + (size_t)(arow0 + row) * FDIM + ccol + c16 * 8;
        else if (mat == 2) src = g_Whi + (size_t)(brow0 + row) * FDIM + ccol + c16 * 8;
        else               src = g_Wlo + (size_t)(brow0 + row) * FDIM + ccol + c16 * 8;
        cpa16(dst, src);
    }
    CP_COMMIT();
}

__global__ __launch_bounds__(256) void gates_mma(
    const float* __restrict__ c_in,
    const float* __restrict__ b_ih, const float* __restrict__ b_hh,
    float* __restrict__ out)
{
    const int k   = blockIdx.z;
    const int beg = g_off_ci[k];
    const int cnt = g_off_ci[k + 1] - beg;
    const int m0  = blockIdx.x * BM;
    if (m0 >= cnt) return;
    const int n0  = blockIdx.y * BN;

    extern __shared__ char smem[];
    const uint32_t sb = smem_u32(smem);
    const int tid = threadIdx.x;
    const int w   = tid >> 5;
    const int l   = tid & 31;
    const int wm  = w >> 2;        // 0..1
    const int wn  = w & 3;         // 0..3

    // bias for this packed n-tile
    if (tid < 128) {
        int j = n0 + tid;
        int u = j >> 2, gate = j & 3;
        int g = gate * 512 + u;
        ((float*)(smem + SM_BIAS))[tid] = b_ih[k * GDIM + g] + b_hh[k * GDIM + g];
    }

    const int arow0 = beg + m0;
    const int brow0 = k * GDIM + n0;

    float acc[4][4][4];
#pragma unroll
    for (int a = 0; a < 4; a++)
#pragma unroll
        for (int b2 = 0; b2 < 4; b2++)
#pragma unroll
            for (int c = 0; c < 4; c++) acc[a][b2][c] = 0.f;

    load_stage(tid, sb, 0, arow0, brow0, 0);
    load_stage(tid, sb, 1, arow0, brow0, BK);

    const int lr   = l & 15;
    const int lc16 = (l >> 4) << 4;

    for (int s = 0; s < NSTAGES; s++) {
        const int b = s & 1;
        if (s < NSTAGES - 1) cp_wait<1>(); else cp_wait<0>();
        __syncthreads();

        const uint32_t stg = sb + SM_STG + b * STGB;
        const uint32_t aHi = stg, aLo = stg + MATB, bHi = stg + 2 * MATB, bLo = stg + 3 * MATB;

#pragma unroll
        for (int ks = 0; ks < 2; ks++) {
            const int kb = ks * 32 + lc16;
            uint32_t bh[2][4], bl[2][4], af[4][4];
#pragma unroll
            for (int g2 = 0; g2 < 2; g2++) {
                uint32_t brow = wn * 32 + g2 * 16 + lr;
                ldm4(bh[g2], bHi + brow * ROWB + kb);
                ldm4(bl[g2], bLo + brow * ROWB + kb);
            }
#pragma unroll
            for (int mi = 0; mi < 4; mi++) {
                uint32_t arow = wm * 64 + mi * 16 + lr;
                ldm4(af[mi], aHi + arow * ROWB + kb);
            }
            // pass 1: Ahi * Bhi
#pragma unroll
            for (int mi = 0; mi < 4; mi++)
#pragma unroll
                for (int ni = 0; ni < 4; ni++)
                    mma16816(acc[mi][ni], af[mi], bh[ni >> 1][ni & 1], bh[ni >> 1][(ni & 1) + 2]);
            // pass 2: Ahi * Blo
#pragma unroll
            for (int mi = 0; mi < 4; mi++)
#pragma unroll
                for (int ni = 0; ni < 4; ni++)
                    mma16816(acc[mi][ni], af[mi], bl[ni >> 1][ni & 1], bl[ni >> 1][(ni & 1) + 2]);
            // pass 3: Alo * Bhi (reuse af regs)
#pragma unroll
            for (int mi = 0; mi < 4; mi++) {
                uint32_t arow = wm * 64 + mi * 16 + lr;
                ldm4(af[mi], aLo + arow * ROWB + kb);
            }
#pragma unroll
            for (int mi = 0; mi < 4; mi++)
#pragma unroll
                for (int ni = 0; ni < 4; ni++)
                    mma16816(acc[mi][ni], af[mi], bh[ni >> 1][ni & 1], bh[ni >> 1][(ni & 1) + 2]);
        }

        __syncthreads();
        if (s + 2 < NSTAGES) load_stage(tid, sb, b, arow0, brow0, (s + 2) * BK);
    }

    // -------- epilogue: acc -> smem f32 tile -> fused LSTM --------
    float* ep = (float*)(smem + SM_STG);
#pragma unroll
    for (int mi = 0; mi < 4; mi++)
#pragma unroll
        for (int ni = 0; ni < 4; ni++) {
            int r0 = wm * 64 + mi * 16 + (l >> 2);
            int c0 = wn * 32 + ni * 8 + (l & 3) * 2;
            *(float2*)&ep[r0 * EPW + c0]       = make_float2(acc[mi][ni][0], acc[mi][ni][1]);
            *(float2*)&ep[(r0 + 8) * EPW + c0] = make_float2(acc[mi][ni][2], acc[mi][ni][3]);
        }
    __syncthreads();

    {
        const float* bias = (const float*)(smem + SM_BIAS);
        const int row = tid >> 1;            // 0..127
        const int uu0 = (tid & 1) * 16;
        const int m = m0 + row;
        if (m < cnt) {
            const int t  = g_perm_ci[beg + m];
            const int u0 = n0 >> 2;
            const size_t OFF_H = (size_t)NTOK * CCH;
            const size_t OFF_C = OFF_H + (size_t)NTOK * HDIM;
#pragma unroll
            for (int j = 0; j < 16; j++) {
                int uu = uu0 + j;
                float4 v = *(const float4*)&ep[row * EPW + uu * 4];
                float iv = v.x + bias[4 * uu + 0];
                float fv = v.y + bias[4 * uu + 1];
                float gv = v.z + bias[4 * uu + 2];
                float ov = v.w + bias[4 * uu + 3];
                int u = u0 + uu;
                float cold = c_in[(size_t)t * HDIM + u];
                float si = 1.f / (1.f + expf(-iv));
                float sf = 1.f / (1.f + expf(-fv));
                float so = 1.f / (1.f + expf(-ov));
                float c2 = sf * cold + si * tanhf(gv);
                float h2 = so * tanhf(c2);
                out[OFF_H + (size_t)t * HDIM + u] = h2;
                out[OFF_C + (size_t)t * HDIM + u] = c2;
            }
        }
    }
}

// ---------------- log_odds SIMT GEMM (fp32) ----------------
__global__ __launch_bounds__(256) void logodds_gemm(
    const float* __restrict__ et,
    const float* __restrict__ W_lin, const float* __restrict__ b_lin,
    float* __restrict__ out)
{
    const int kc  = blockIdx.z;
    const int beg = g_off_cat[kc];
    const int cnt = g_off_cat[kc + 1] - beg;
    const int m0  = blockIdx.x * 64;
    if (m0 >= cnt) return;
    const int n0  = blockIdx.y * 64;

    __shared__ float As[16][68];
    __shared__ float Bs[16][68];

    const int tid = threadIdx.x;
    const int tx  = tid & 15;
    const int ty  = tid >> 4;
    const int lr  = tid >> 2;
    const int lc  = (tid & 3) * 4;

    int tA = -1;
    if (m0 + lr < cnt) tA = g_perm_cat[beg + m0 + lr];
    const size_t wrow = ((size_t)kc * CCH + (n0 + lr)) * HDIM;

    float acc[4][4];
#pragma unroll
    for (int i = 0; i < 4; i++)
#pragma unroll
        for (int j = 0; j < 4; j++) acc[i][j] = 0.f;

    for (int ib = 0; ib < HDIM; ib += 16) {
        const int ii = ib + lc;
        float4 va = make_float4(0.f, 0.f, 0.f, 0.f);
        if (tA >= 0) va = *(const float4*)(et + (size_t)tA * HDIM + ii);
        float4 vb = *(const float4*)(W_lin + wrow + ii);

        As[lc + 0][lr] = va.x; As[lc + 1][lr] = va.y;
        As[lc + 2][lr] = va.z; As[lc + 3][lr] = va.w;
        Bs[lc + 0][lr] = vb.x; Bs[lc + 1][lr] = vb.y;
        Bs[lc + 2][lr] = vb.z; Bs[lc + 3][lr] = vb.w;
        __syncthreads();

#pragma unroll
        for (int kk = 0; kk < 16; kk++) {
            float4 a4 = *(const float4*)&As[kk][ty * 4];
            float4 b4 = *(const float4*)&Bs[kk][tx * 4];
            float a[4] = {a4.x, a4.y, a4.z, a4.w};
            float b[4] = {b4.x, b4.y, b4.z, b4.w};
#pragma unroll
            for (int i = 0; i < 4; i++)
#pragma unroll
                for (int j = 0; j < 4; j++)
                    acc[i][j] = fmaf(a[i], b[j], acc[i][j]);
        }
        __syncthreads();
    }

#pragma unroll
    for (int i = 0; i < 4; i++) {
        int m = m0 + ty * 4 + i;
        if (m < cnt) {
            int t = g_perm_cat[beg + m];
#pragma unroll
            for (int j = 0; j < 4; j++) {
                int g = n0 + tx * 4 + j;
                out[(size_t)t * CCH + g] = acc[i][j] + b_lin[kc * CCH + g];
            }
        }
    }
}

// ---------------- launch ----------------
extern "C" void kernel_launch(void* const* d_in, const int* in_sizes, int n_in,
                              void* d_out, int out_size) {
    const float* et    = (const float*)d_in[0];
    const float* x     = (const float*)d_in[1];
    const float* h     = (const float*)d_in[2];
    const float* c     = (const float*)d_in[3];
    const int*   cat   = (const int*)d_in[4];
    const int*   ci    = (const int*)d_in[5];
    const float* W_lin = (const float*)d_in[6];
    const float* b_lin = (const float*)d_in[7];
    const float* W_ih  = (const float*)d_in[8];
    const float* W_hh  = (const float*)d_in[9];
    const float* b_ih  = (const float*)d_in[10];
    const float* b_hh  = (const float*)d_in[11];
    float* out = (float*)d_out;

    cudaFuncSetAttribute(gates_mma, cudaFuncAttributeMaxDynamicSharedMemorySize, SM_TOTAL);

    k_zero<<<1, 64>>>();
    k_hist<<<NTOK / 256, 256>>>(cat, ci);
    k_scan<<<1, 1>>>();
    k_scatter<<<NTOK / 256, 256>>>(cat, ci);

    pack_W<<<MCI * GDIM, 128>>>(W_ih, W_hh);
    pack_A<<<NTOK, 128>>>(x, h);

    logodds_gemm<<<dim3(NTOK / 64, CCH / 64, KCAT), 256>>>(et, W_lin, b_lin, out);

    gates_mma<<<dim3(NTOK / BM, GDIM / BN, MCI), 256, SM_TOTAL>>>(c, b_ih, b_hh, out);
}

// round 10
// speedup vs baseline: 2.5914x; 1.2348x over previous
#include <cuda_runtime.h>
#include <cuda_fp16.h>
#include <math.h>
#include <stdint.h>

// Problem constants
#define NTOK  4096
#define HDIM  512
#define CCH   128
#define KCAT  64
#define MCI   4
#define INDIM 1024
#define GDIM  2048      // 4*H
#define FDIM  1536      // INDIM + HDIM
#define APAD  4224      // NTOK + 128 tile slack

// gates GEMM tiling
#define BM 128
#define BN 128
#define BK 32
#define NSTAGES (FDIM / BK)     // 48
#define ROWB 80                 // padded row bytes (32 fp16 = 64B data + 16B pad)
#define MATB (BM * ROWB)        // 10240 bytes per matrix tile
#define STGB (3 * MATB)         // Ahi, Alo, B   (30720)
#define SM_BIAS 512
#define SM_STG  1024
#define EPW 136                 // epilogue f32 row stride (floats)
#define SM_TOTAL (SM_STG + BM * EPW * 4)   // 70656 (covers 2*STGB=61440 stages too)

// ---------------- device scratch (static) ----------------
__device__ __half g_Ahi[(size_t)APAD * FDIM];
__device__ __half g_Alo[(size_t)APAD * FDIM];
__device__ __half g_W[(size_t)MCI * GDIM * FDIM];
__device__ int g_perm_ci[NTOK];
__device__ int g_perm_cat[NTOK];
__device__ int g_off_ci[MCI + 1];
__device__ int g_off_cat[KCAT + 1];

// ---------------- PTX helpers (sm_80-level only) ----------------
__device__ __forceinline__ uint32_t smem_u32(const void* p) {
    uint32_t a;
    asm("{ .reg .u64 t; cvta.to.shared.u64 t, %1; cvt.u32.u64 %0, t; }" : "=r"(a) : "l"(p));
    return a;
}
__device__ __forceinline__ void cpa16(uint32_t dst, const void* src) {
    asm volatile("cp.async.cg.shared.global [%0], [%1], 16;" :: "r"(dst), "l"(src));
}
#define CP_COMMIT() asm volatile("cp.async.commit_group;" ::: "memory")
template <int N> __device__ __forceinline__ void cp_wait() {
    asm volatile("cp.async.wait_group %0;" :: "n"(N) : "memory");
}
__device__ __forceinline__ void ldm4(uint32_t* r, uint32_t addr) {
    asm volatile("ldmatrix.sync.aligned.m8n8.x4.shared.b16 {%0,%1,%2,%3}, [%4];"
        : "=r"(r[0]), "=r"(r[1]), "=r"(r[2]), "=r"(r[3]) : "r"(addr));
}
__device__ __forceinline__ void mma16816(float* c, const uint32_t* a, uint32_t b0, uint32_t b1) {
    asm volatile(
        "mma.sync.aligned.m16n8k16.row.col.f32.f16.f16.f32 "
        "{%0,%1,%2,%3}, {%4,%5,%6,%7}, {%8,%9}, {%0,%1,%2,%3};"
        : "+f"(c[0]), "+f"(c[1]), "+f"(c[2]), "+f"(c[3])
        : "r"(a[0]), "r"(a[1]), "r"(a[2]), "r"(a[3]), "r"(b0), "r"(b1));
}

// ---------------- fused single-block counting sort ----------------
__global__ __launch_bounds__(1024) void k_sort(const int* __restrict__ cat,
                                               const int* __restrict__ ci) {
    __shared__ int s_ci[MCI], s_cat[KCAT], p_ci[MCI], p_cat[KCAT];
    const int tid = threadIdx.x;
    if (tid < MCI)  s_ci[tid]  = 0;
    if (tid < KCAT) s_cat[tid] = 0;
    __syncthreads();
    for (int n = tid; n < NTOK; n += 1024) {
        atomicAdd(&s_ci[ci[n]], 1);
        atomicAdd(&s_cat[cat[n]], 1);
    }
    __syncthreads();
    if (tid == 0) {
        int s = 0;
        for (int i = 0; i < MCI; i++) { g_off_ci[i] = s; p_ci[i] = s; s += s_ci[i]; }
        g_off_ci[MCI] = s;
    }
    if (tid == 32) {
        int s = 0;
        for (int i = 0; i < KCAT; i++) { g_off_cat[i] = s; p_cat[i] = s; s += s_cat[i]; }
        g_off_cat[KCAT] = s;
    }
    __syncthreads();
    for (int n = tid; n < NTOK; n += 1024) {
        g_perm_ci[atomicAdd(&p_ci[ci[n]], 1)] = n;
        g_perm_cat[atomicAdd(&p_cat[cat[n]], 1)] = n;
    }
}

// ---------------- pack activations: hi/lo fp16 of permuted [x|h] ----------------
__global__ __launch_bounds__(128) void pack_A(const float* __restrict__ x,
                                              const float* __restrict__ h) {
    const int p = blockIdx.x;
    const int t = g_perm_ci[p];
    const int tid = threadIdx.x;
#pragma unroll
    for (int r = 0; r < 3; r++) {
        int col = (tid + 128 * r) * 4;
        float4 v = (col < INDIM)
                 ? *(const float4*)(x + (size_t)t * INDIM + col)
                 : *(const float4*)(h + (size_t)t * HDIM + (col - INDIM));
        float vv[4] = {v.x, v.y, v.z, v.w};
        ushort4 hi, lo;
        unsigned short* hp = &hi.x;
        unsigned short* lp = &lo.x;
#pragma unroll
        for (int j = 0; j < 4; j++) {
            __half hb = __float2half_rn(vv[j]);
            __half lb = __float2half_rn(vv[j] - __half2float(hb));
            hp[j] = __half_as_ushort(hb);
            lp[j] = __half_as_ushort(lb);
        }
        *(ushort4*)(g_Ahi + (size_t)p * FDIM + col) = hi;
        *(ushort4*)(g_Alo + (size_t)p * FDIM + col) = lo;
    }
}

// ---------------- pack weights (single fp16): row R = k*2048 + 4*u + gate ----------------
__global__ __launch_bounds__(128) void pack_W(const float* __restrict__ W_ih,
                                              const float* __restrict__ W_hh) {
    const int R = blockIdx.x;            // 0..8191
    const int k = R >> 11;
    const int r = R & 2047;
    const int u = r >> 2;
    const int gate = r & 3;
    const int g = gate * 512 + u;
    const int tid = threadIdx.x;
    const float* src_ih = W_ih + ((size_t)k * GDIM + g) * INDIM;
    const float* src_hh = W_hh + ((size_t)k * GDIM + g) * HDIM;
#pragma unroll
    for (int rr = 0; rr < 3; rr++) {
        int col = (tid + 128 * rr) * 4;
        float4 v = (col < INDIM) ? *(const float4*)(src_ih + col)
                                 : *(const float4*)(src_hh + (col - INDIM));
        float vv[4] = {v.x, v.y, v.z, v.w};
        ushort4 w4;
        unsigned short* wp = &w4.x;
#pragma unroll
        for (int j = 0; j < 4; j++)
            wp[j] = __half_as_ushort(__float2half_rn(vv[j]));
        *(ushort4*)(g_W + (size_t)R * FDIM + col) = w4;
    }
}

// ---------------- gates HMMA GEMM (fp16 2-pass) + fused LSTM epilogue ----------------
__device__ __forceinline__ void load_stage(int tid, uint32_t sb, int b,
                                           int arow0, int brow0, int ccol) {
#pragma unroll
    for (int i = 0; i < 6; i++) {
        int cidx = tid + 256 * i;        // 0..1535
        int mat  = cidx >> 9;            // 0=Ahi 1=Alo 2=B
        int cc   = cidx & 511;
        int row  = cc >> 2;
        int c16  = cc & 3;
        uint32_t dst = sb + SM_STG + b * STGB + mat * MATB + row * ROWB + c16 * 16;
        const __half* src;
        if (mat == 0)      src = g_Ahi + (size_t)(arow0 + row) * FDIM + ccol + c16 * 8;
        else if (mat == 1) src = g_Alo + (size_t)(arow0 + row) * FDIM + ccol + c16 * 8;
        else               src = g_W   + (size_t)(brow0 + row) * FDIM + ccol + c16 * 8;
        cpa16(dst, src);
    }
    CP_COMMIT();
}

__global__ __launch_bounds__(256, 2) void gates_mma(
    const float* __restrict__ c_in,
    const float* __restrict__ b_ih, const float* __restrict__ b_hh,
    float* __restrict__ out)
{
    const int k   = blockIdx.z;
    const int beg = g_off_ci[k];
    const int cnt = g_off_ci[k + 1] - beg;
    const int m0  = blockIdx.x * BM;
    if (m0 >= cnt) return;
    const int n0  = blockIdx.y * BN;

    extern __shared__ char smem[];
    const uint32_t sb = smem_u32(smem);
    const int tid = threadIdx.x;
    const int w   = tid >> 5;
    const int l   = tid & 31;
    const int wm  = w >> 2;        // 0..1
    const int wn  = w & 3;         // 0..3

    if (tid < 128) {
        int j = n0 + tid;
        int u = j >> 2, gate = j & 3;
        int g = gate * 512 + u;
        ((float*)(smem + SM_BIAS))[tid] = b_ih[k * GDIM + g] + b_hh[k * GDIM + g];
    }

    const int arow0 = beg + m0;
    const int brow0 = k * GDIM + n0;

    float acc[4][4][4];
#pragma unroll
    for (int a = 0; a < 4; a++)
#pragma unroll
        for (int b2 = 0; b2 < 4; b2++)
#pragma unroll
            for (int c = 0; c < 4; c++) acc[a][b2][c] = 0.f;

    load_stage(tid, sb, 0, arow0, brow0, 0);
    load_stage(tid, sb, 1, arow0, brow0, BK);

    const int lr   = l & 15;
    const int lc16 = (l >> 4) << 4;

    for (int s = 0; s < NSTAGES; s++) {
        const int b = s & 1;
        if (s < NSTAGES - 1) cp_wait<1>(); else cp_wait<0>();
        __syncthreads();

        const uint32_t stg = sb + SM_STG + b * STGB;
        const uint32_t aHi = stg, aLo = stg + MATB, bB = stg + 2 * MATB;

#pragma unroll
        for (int ks = 0; ks < 2; ks++) {
            const int kb = ks * 32 + lc16;
            uint32_t bb[2][4], af[4][4];
#pragma unroll
            for (int g2 = 0; g2 < 2; g2++) {
                uint32_t brow = wn * 32 + g2 * 16 + lr;
                ldm4(bb[g2], bB + brow * ROWB + kb);
            }
            // pass 1: Ahi * B
#pragma unroll
            for (int mi = 0; mi < 4; mi++) {
                uint32_t arow = wm * 64 + mi * 16 + lr;
                ldm4(af[mi], aHi + arow * ROWB + kb);
            }
#pragma unroll
            for (int mi = 0; mi < 4; mi++)
#pragma unroll
                for (int ni = 0; ni < 4; ni++)
                    mma16816(acc[mi][ni], af[mi], bb[ni >> 1][ni & 1], bb[ni >> 1][(ni & 1) + 2]);
            // pass 2: Alo * B
#pragma unroll
            for (int mi = 0; mi < 4; mi++) {
                uint32_t arow = wm * 64 + mi * 16 + lr;
                ldm4(af[mi], aLo + arow * ROWB + kb);
            }
#pragma unroll
            for (int mi = 0; mi < 4; mi++)
#pragma unroll
                for (int ni = 0; ni < 4; ni++)
                    mma16816(acc[mi][ni], af[mi], bb[ni >> 1][ni & 1], bb[ni >> 1][(ni & 1) + 2]);
        }

        __syncthreads();
        if (s + 2 < NSTAGES) load_stage(tid, sb, b, arow0, brow0, (s + 2) * BK);
    }

    // -------- epilogue: acc -> smem f32 tile -> fused LSTM --------
    float* ep = (float*)(smem + SM_STG);
#pragma unroll
    for (int mi = 0; mi < 4; mi++)
#pragma unroll
        for (int ni = 0; ni < 4; ni++) {
            int r0 = wm * 64 + mi * 16 + (l >> 2);
            int c0 = wn * 32 + ni * 8 + (l & 3) * 2;
            *(float2*)&ep[r0 * EPW + c0]       = make_float2(acc[mi][ni][0], acc[mi][ni][1]);
            *(float2*)&ep[(r0 + 8) * EPW + c0] = make_float2(acc[mi][ni][2], acc[mi][ni][3]);
        }
    __syncthreads();

    {
        const float* bias = (const float*)(smem + SM_BIAS);
        const int row = tid >> 1;            // 0..127
        const int uu0 = (tid & 1) * 16;
        const int m = m0 + row;
        if (m < cnt) {
            const int t  = g_perm_ci[beg + m];
            const int u0 = n0 >> 2;
            const size_t OFF_H = (size_t)NTOK * CCH;
            const size_t OFF_C = OFF_H + (size_t)NTOK * HDIM;
#pragma unroll
            for (int j = 0; j < 16; j++) {
                int uu = uu0 + j;
                float4 v = *(const float4*)&ep[row * EPW + uu * 4];
                float iv = v.x + bias[4 * uu + 0];
                float fv = v.y + bias[4 * uu + 1];
                float gv = v.z + bias[4 * uu + 2];
                float ov = v.w + bias[4 * uu + 3];
                int u = u0 + uu;
                float cold = c_in[(size_t)t * HDIM + u];
                float si = 1.f / (1.f + expf(-iv));
                float sf = 1.f / (1.f + expf(-fv));
                float so = 1.f / (1.f + expf(-ov));
                float c2 = sf * cold + si * tanhf(gv);
                float h2 = so * tanhf(c2);
                out[OFF_H + (size_t)t * HDIM + u] = h2;
                out[OFF_C + (size_t)t * HDIM + u] = c2;
            }
        }
    }
}

// ---------------- log_odds SIMT GEMM (fp32) ----------------
__global__ __launch_bounds__(256) void logodds_gemm(
    const float* __restrict__ et,
    const float* __restrict__ W_lin, const float* __restrict__ b_lin,
    float* __restrict__ out)
{
    const int kc  = blockIdx.z;
    const int beg = g_off_cat[kc];
    const int cnt = g_off_cat[kc + 1] - beg;
    const int m0  = blockIdx.x * 64;
    if (m0 >= cnt) return;
    const int n0  = blockIdx.y * 64;

    __shared__ float As[16][68];
    __shared__ float Bs[16][68];

    const int tid = threadIdx.x;
    const int tx  = tid & 15;
    const int ty  = tid >> 4;
    const int lr  = tid >> 2;
    const int lc  = (tid & 3) * 4;

    int tA = -1;
    if (m0 + lr < cnt) tA = g_perm_cat[beg + m0 + lr];
    const size_t wrow = ((size_t)kc * CCH + (n0 + lr)) * HDIM;

    float acc[4][4];
#pragma unroll
    for (int i = 0; i < 4; i++)
#pragma unroll
        for (int j = 0; j < 4; j++) acc[i][j] = 0.f;

    for (int ib = 0; ib < HDIM; ib += 16) {
        const int ii = ib + lc;
        float4 va = make_float4(0.f, 0.f, 0.f, 0.f);
        if (tA >= 0) va = *(const float4*)(et + (size_t)tA * HDIM + ii);
        float4 vb = *(const float4*)(W_lin + wrow + ii);

        As[lc + 0][lr] = va.x; As[lc + 1][lr] = va.y;
        As[lc + 2][lr] = va.z; As[lc + 3][lr] = va.w;
        Bs[lc + 0][lr] = vb.x; Bs[lc + 1][lr] = vb.y;
        Bs[lc + 2][lr] = vb.z; Bs[lc + 3][lr] = vb.w;
        __syncthreads();

#pragma unroll
        for (int kk = 0; kk < 16; kk++) {
            float4 a4 = *(const float4*)&As[kk][ty * 4];
            float4 b4 = *(const float4*)&Bs[kk][tx * 4];
            float a[4] = {a4.x, a4.y, a4.z, a4.w};
            float b[4] = {b4.x, b4.y, b4.z, b4.w};
#pragma unroll
            for (int i = 0; i < 4; i++)
#pragma unroll
                for (int j = 0; j < 4; j++)
                    acc[i][j] = fmaf(a[i], b[j], acc[i][j]);
        }
        __syncthreads();
    }

#pragma unroll
    for (int i = 0; i < 4; i++) {
        int m = m0 + ty * 4 + i;
        if (m < cnt) {
            int t = g_perm_cat[beg + m];
#pragma unroll
            for (int j = 0; j < 4; j++) {
                int g = n0 + tx * 4 + j;
                out[(size_t)t * CCH + g] = acc[i][j] + b_lin[kc * CCH + g];
            }
        }
    }
}

// ---------------- launch ----------------
extern "C" void kernel_launch(void* const* d_in, const int* in_sizes, int n_in,
                              void* d_out, int out_size) {
    const float* et    = (const float*)d_in[0];
    const float* x     = (const float*)d_in[1];
    const float* h     = (const float*)d_in[2];
    const float* c     = (const float*)d_in[3];
    const int*   cat   = (const int*)d_in[4];
    const int*   ci    = (const int*)d_in[5];
    const float* W_lin = (const float*)d_in[6];
    const float* b_lin = (const float*)d_in[7];
    const float* W_ih  = (const float*)d_in[8];
    const float* W_hh  = (const float*)d_in[9];
    const float* b_ih  = (const float*)d_in[10];
    const float* b_hh  = (const float*)d_in[11];
    float* out = (float*)d_out;

    cudaFuncSetAttribute(gates_mma, cudaFuncAttributeMaxDynamicSharedMemorySize, SM_TOTAL);

    k_sort<<<1, 1024>>>(cat, ci);

    pack_W<<<MCI * GDIM, 128>>>(W_ih, W_hh);
    pack_A<<<NTOK, 128>>>(x, h);

    logodds_gemm<<<dim3(NTOK / 64, CCH / 64, KCAT), 256>>>(et, W_lin, b_lin, out);

    gates_mma<<<dim3(NTOK / BM, GDIM / BN, MCI), 256, SM_TOTAL>>>(c, b_ih, b_hh, out);
}

// round 11
// speedup vs baseline: 2.9928x; 1.1549x over previous
#include <cuda_runtime.h>
#include <cuda_fp16.h>
#include <math.h>
#include <stdint.h>

// Problem constants
#define NTOK  4096
#define HDIM  512
#define CCH   128
#define KCAT  64
#define MCI   4
#define INDIM 1024
#define GDIM  2048      // 4*H
#define FDIM  1536      // INDIM + HDIM
#define APAD  4224      // NTOK + 128 tile slack

// gates GEMM tiling
#define BM 128
#define BN 128
#define BK 32
#define NSTAGES (FDIM / BK)     // 48
#define ROWB 80                 // padded row bytes (32 fp16 = 64B data + 16B pad)
#define MATB (BM * ROWB)        // 10240 bytes per matrix tile
#define STGB (3 * MATB)         // Ahi, Alo, B   (30720)
#define SM_BIAS 512
#define SM_STG  1024
#define EPW 136                 // epilogue f32 row stride (floats)
#define SM_TOTAL (SM_STG + BM * EPW * 4)   // 70656 (covers 2*STGB=61440 stages too)

// logodds GEMM tiling
#define LBM 64
#define LBN 128
#define LBK 32
#define LNST (HDIM / LBK)       // 16
#define LMATE (LBM * ROWB)      // 5120
#define LMATW (LBN * ROWB)      // 10240
#define LSTG  (2 * LMATE + LMATW)   // 20480
#define LSM_TOTAL (512 + 2 * LSTG)  // 41472

// ---------------- device scratch (static) ----------------
__device__ __half g_Ahi[(size_t)APAD * FDIM];
__device__ __half g_Alo[(size_t)APAD * FDIM];
__device__ __half g_W[(size_t)MCI * GDIM * FDIM];
__device__ __half g_Ehi[(size_t)APAD * HDIM];
__device__ __half g_Elo[(size_t)APAD * HDIM];
__device__ __half g_WL[(size_t)KCAT * CCH * HDIM];
__device__ int g_perm_ci[NTOK];
__device__ int g_perm_cat[NTOK];
__device__ int g_off_ci[MCI + 1];
__device__ int g_off_cat[KCAT + 1];

// ---------------- PTX helpers (sm_80-level only) ----------------
__device__ __forceinline__ uint32_t smem_u32(const void* p) {
    uint32_t a;
    asm("{ .reg .u64 t; cvta.to.shared.u64 t, %1; cvt.u32.u64 %0, t; }" : "=r"(a) : "l"(p));
    return a;
}
__device__ __forceinline__ void cpa16(uint32_t dst, const void* src) {
    asm volatile("cp.async.cg.shared.global [%0], [%1], 16;" :: "r"(dst), "l"(src));
}
#define CP_COMMIT() asm volatile("cp.async.commit_group;" ::: "memory")
template <int N> __device__ __forceinline__ void cp_wait() {
    asm volatile("cp.async.wait_group %0;" :: "n"(N) : "memory");
}
__device__ __forceinline__ void ldm4(uint32_t* r, uint32_t addr) {
    asm volatile("ldmatrix.sync.aligned.m8n8.x4.shared.b16 {%0,%1,%2,%3}, [%4];"
        : "=r"(r[0]), "=r"(r[1]), "=r"(r[2]), "=r"(r[3]) : "r"(addr));
}
__device__ __forceinline__ void mma16816(float* c, const uint32_t* a, uint32_t b0, uint32_t b1) {
    asm volatile(
        "mma.sync.aligned.m16n8k16.row.col.f32.f16.f16.f32 "
        "{%0,%1,%2,%3}, {%4,%5,%6,%7}, {%8,%9}, {%0,%1,%2,%3};"
        : "+f"(c[0]), "+f"(c[1]), "+f"(c[2]), "+f"(c[3])
        : "r"(a[0]), "r"(a[1]), "r"(a[2]), "r"(a[3]), "r"(b0), "r"(b1));
}

// ---------------- fused single-block counting sort ----------------
__global__ __launch_bounds__(1024) void k_sort(const int* __restrict__ cat,
                                               const int* __restrict__ ci) {
    __shared__ int s_ci[MCI], s_cat[KCAT], p_ci[MCI], p_cat[KCAT];
    const int tid = threadIdx.x;
    if (tid < MCI)  s_ci[tid]  = 0;
    if (tid < KCAT) s_cat[tid] = 0;
    __syncthreads();
    for (int n = tid; n < NTOK; n += 1024) {
        atomicAdd(&s_ci[ci[n]], 1);
        atomicAdd(&s_cat[cat[n]], 1);
    }
    __syncthreads();
    if (tid == 0) {
        int s = 0;
        for (int i = 0; i < MCI; i++) { g_off_ci[i] = s; p_ci[i] = s; s += s_ci[i]; }
        g_off_ci[MCI] = s;
    }
    if (tid == 32) {
        int s = 0;
        for (int i = 0; i < KCAT; i++) { g_off_cat[i] = s; p_cat[i] = s; s += s_cat[i]; }
        g_off_cat[KCAT] = s;
    }
    __syncthreads();
    for (int n = tid; n < NTOK; n += 1024) {
        g_perm_ci[atomicAdd(&p_ci[ci[n]], 1)] = n;
        g_perm_cat[atomicAdd(&p_cat[cat[n]], 1)] = n;
    }
}

// ---------------- pack activations: hi/lo fp16 of permuted [x|h] ----------------
__global__ __launch_bounds__(128) void pack_A(const float* __restrict__ x,
                                              const float* __restrict__ h) {
    const int p = blockIdx.x;
    const int t = g_perm_ci[p];
    const int tid = threadIdx.x;
#pragma unroll
    for (int r = 0; r < 3; r++) {
        int col = (tid + 128 * r) * 4;
        float4 v = (col < INDIM)
                 ? *(const float4*)(x + (size_t)t * INDIM + col)
                 : *(const float4*)(h + (size_t)t * HDIM + (col - INDIM));
        float vv[4] = {v.x, v.y, v.z, v.w};
        ushort4 hi, lo;
        unsigned short* hp = &hi.x;
        unsigned short* lp = &lo.x;
#pragma unroll
        for (int j = 0; j < 4; j++) {
            __half hb = __float2half_rn(vv[j]);
            __half lb = __float2half_rn(vv[j] - __half2float(hb));
            hp[j] = __half_as_ushort(hb);
            lp[j] = __half_as_ushort(lb);
        }
        *(ushort4*)(g_Ahi + (size_t)p * FDIM + col) = hi;
        *(ushort4*)(g_Alo + (size_t)p * FDIM + col) = lo;
    }
}

// ---------------- pack et: hi/lo fp16 in cat-perm order ----------------
__global__ __launch_bounds__(128) void pack_E(const float* __restrict__ et) {
    const int p = blockIdx.x;
    const int t = g_perm_cat[p];
    const int tid = threadIdx.x;
    int col = tid * 4;
    float4 v = *(const float4*)(et + (size_t)t * HDIM + col);
    float vv[4] = {v.x, v.y, v.z, v.w};
    ushort4 hi, lo;
    unsigned short* hp = &hi.x;
    unsigned short* lp = &lo.x;
#pragma unroll
    for (int j = 0; j < 4; j++) {
        __half hb = __float2half_rn(vv[j]);
        __half lb = __float2half_rn(vv[j] - __half2float(hb));
        hp[j] = __half_as_ushort(hb);
        lp[j] = __half_as_ushort(lb);
    }
    *(ushort4*)(g_Ehi + (size_t)p * HDIM + col) = hi;
    *(ushort4*)(g_Elo + (size_t)p * HDIM + col) = lo;
}

// ---------------- pack weights (single fp16): row R = k*2048 + 4*u + gate ----------------
__global__ __launch_bounds__(128) void pack_W(const float* __restrict__ W_ih,
                                              const float* __restrict__ W_hh) {
    const int R = blockIdx.x;            // 0..8191
    const int k = R >> 11;
    const int r = R & 2047;
    const int u = r >> 2;
    const int gate = r & 3;
    const int g = gate * 512 + u;
    const int tid = threadIdx.x;
    const float* src_ih = W_ih + ((size_t)k * GDIM + g) * INDIM;
    const float* src_hh = W_hh + ((size_t)k * GDIM + g) * HDIM;
#pragma unroll
    for (int rr = 0; rr < 3; rr++) {
        int col = (tid + 128 * rr) * 4;
        float4 v = (col < INDIM) ? *(const float4*)(src_ih + col)
                                 : *(const float4*)(src_hh + (col - INDIM));
        float vv[4] = {v.x, v.y, v.z, v.w};
        ushort4 w4;
        unsigned short* wp = &w4.x;
#pragma unroll
        for (int j = 0; j < 4; j++)
            wp[j] = __half_as_ushort(__float2half_rn(vv[j]));
        *(ushort4*)(g_W + (size_t)R * FDIM + col) = w4;
    }
}

// ---------------- pack W_lin -> fp16 ----------------
__global__ __launch_bounds__(128) void pack_WL(const float* __restrict__ W_lin) {
    const int R = blockIdx.x;            // 0..8191 = kc*128 + cch
    const int tid = threadIdx.x;
    int col = tid * 4;
    float4 v = *(const float4*)(W_lin + (size_t)R * HDIM + col);
    float vv[4] = {v.x, v.y, v.z, v.w};
    ushort4 w4;
    unsigned short* wp = &w4.x;
#pragma unroll
    for (int j = 0; j < 4; j++)
        wp[j] = __half_as_ushort(__float2half_rn(vv[j]));
    *(ushort4*)(g_WL + (size_t)R * HDIM + col) = w4;
}

// ---------------- gates HMMA GEMM (fp16 2-pass) + fused LSTM epilogue ----------------
__device__ __forceinline__ void load_stage(int tid, uint32_t sb, int b,
                                           int arow0, int brow0, int ccol) {
#pragma unroll
    for (int i = 0; i < 6; i++) {
        int cidx = tid + 256 * i;        // 0..1535
        int mat  = cidx >> 9;            // 0=Ahi 1=Alo 2=B
        int cc   = cidx & 511;
        int row  = cc >> 2;
        int c16  = cc & 3;
        uint32_t dst = sb + SM_STG + b * STGB + mat * MATB + row * ROWB + c16 * 16;
        const __half* src;
        if (mat == 0)      src = g_Ahi + (size_t)(arow0 + row) * FDIM + ccol + c16 * 8;
        else if (mat == 1) src = g_Alo + (size_t)(arow0 + row) * FDIM + ccol + c16 * 8;
        else               src = g_W   + (size_t)(brow0 + row) * FDIM + ccol + c16 * 8;
        cpa16(dst, src);
    }
    CP_COMMIT();
}

__global__ __launch_bounds__(256, 2) void gates_mma(
    const float* __restrict__ c_in,
    const float* __restrict__ b_ih, const float* __restrict__ b_hh,
    float* __restrict__ out)
{
    const int k   = blockIdx.z;
    const int beg = g_off_ci[k];
    const int cnt = g_off_ci[k + 1] - beg;
    const int m0  = blockIdx.x * BM;
    if (m0 >= cnt) return;
    const int n0  = blockIdx.y * BN;

    extern __shared__ char smem[];
    const uint32_t sb = smem_u32(smem);
    const int tid = threadIdx.x;
    const int w   = tid >> 5;
    const int l   = tid & 31;
    const int wm  = w >> 2;
    const int wn  = w & 3;

    if (tid < 128) {
        int j = n0 + tid;
        int u = j >> 2, gate = j & 3;
        int g = gate * 512 + u;
        ((float*)(smem + SM_BIAS))[tid] = b_ih[k * GDIM + g] + b_hh[k * GDIM + g];
    }

    const int arow0 = beg + m0;
    const int brow0 = k * GDIM + n0;

    float acc[4][4][4];
#pragma unroll
    for (int a = 0; a < 4; a++)
#pragma unroll
        for (int b2 = 0; b2 < 4; b2++)
#pragma unroll
            for (int c = 0; c < 4; c++) acc[a][b2][c] = 0.f;

    load_stage(tid, sb, 0, arow0, brow0, 0);
    load_stage(tid, sb, 1, arow0, brow0, BK);

    const int lr   = l & 15;
    const int lc16 = (l >> 4) << 4;

    for (int s = 0; s < NSTAGES; s++) {
        const int b = s & 1;
        if (s < NSTAGES - 1) cp_wait<1>(); else cp_wait<0>();
        __syncthreads();

        const uint32_t stg = sb + SM_STG + b * STGB;
        const uint32_t aHi = stg, aLo = stg + MATB, bB = stg + 2 * MATB;

#pragma unroll
        for (int ks = 0; ks < 2; ks++) {
            const int kb = ks * 32 + lc16;
            uint32_t bb[2][4], af[4][4];
#pragma unroll
            for (int g2 = 0; g2 < 2; g2++) {
                uint32_t brow = wn * 32 + g2 * 16 + lr;
                ldm4(bb[g2], bB + brow * ROWB + kb);
            }
#pragma unroll
            for (int mi = 0; mi < 4; mi++) {
                uint32_t arow = wm * 64 + mi * 16 + lr;
                ldm4(af[mi], aHi + arow * ROWB + kb);
            }
#pragma unroll
            for (int mi = 0; mi < 4; mi++)
#pragma unroll
                for (int ni = 0; ni < 4; ni++)
                    mma16816(acc[mi][ni], af[mi], bb[ni >> 1][ni & 1], bb[ni >> 1][(ni & 1) + 2]);
#pragma unroll
            for (int mi = 0; mi < 4; mi++) {
                uint32_t arow = wm * 64 + mi * 16 + lr;
                ldm4(af[mi], aLo + arow * ROWB + kb);
            }
#pragma unroll
            for (int mi = 0; mi < 4; mi++)
#pragma unroll
                for (int ni = 0; ni < 4; ni++)
                    mma16816(acc[mi][ni], af[mi], bb[ni >> 1][ni & 1], bb[ni >> 1][(ni & 1) + 2]);
        }

        __syncthreads();
        if (s + 2 < NSTAGES) load_stage(tid, sb, b, arow0, brow0, (s + 2) * BK);
    }

    // -------- epilogue: acc -> smem f32 tile -> fused LSTM --------
    float* ep = (float*)(smem + SM_STG);
#pragma unroll
    for (int mi = 0; mi < 4; mi++)
#pragma unroll
        for (int ni = 0; ni < 4; ni++) {
            int r0 = wm * 64 + mi * 16 + (l >> 2);
            int c0 = wn * 32 + ni * 8 + (l & 3) * 2;
            *(float2*)&ep[r0 * EPW + c0]       = make_float2(acc[mi][ni][0], acc[mi][ni][1]);
            *(float2*)&ep[(r0 + 8) * EPW + c0] = make_float2(acc[mi][ni][2], acc[mi][ni][3]);
        }
    __syncthreads();

    {
        const float* bias = (const float*)(smem + SM_BIAS);
        const int row = tid >> 1;
        const int uu0 = (tid & 1) * 16;
        const int m = m0 + row;
        if (m < cnt) {
            const int t  = g_perm_ci[beg + m];
            const int u0 = n0 >> 2;
            const size_t OFF_H = (size_t)NTOK * CCH;
            const size_t OFF_C = OFF_H + (size_t)NTOK * HDIM;
#pragma unroll
            for (int j = 0; j < 16; j++) {
                int uu = uu0 + j;
                float4 v = *(const float4*)&ep[row * EPW + uu * 4];
                float iv = v.x + bias[4 * uu + 0];
                float fv = v.y + bias[4 * uu + 1];
                float gv = v.z + bias[4 * uu + 2];
                float ov = v.w + bias[4 * uu + 3];
                int u = u0 + uu;
                float cold = c_in[(size_t)t * HDIM + u];
                float si = 1.f / (1.f + expf(-iv));
                float sf = 1.f / (1.f + expf(-fv));
                float so = 1.f / (1.f + expf(-ov));
                float c2 = sf * cold + si * tanhf(gv);
                float h2 = so * tanhf(c2);
                out[OFF_H + (size_t)t * HDIM + u] = h2;
                out[OFF_C + (size_t)t * HDIM + u] = c2;
            }
        }
    }
}

// ---------------- logodds HMMA GEMM (fp16 2-pass) ----------------
__device__ __forceinline__ void load_stage_lo(int tid, uint32_t sb, int b,
                                              int erow0, int wrow0, int ccol) {
#pragma unroll
    for (int i = 0; i < 4; i++) {
        int cidx = tid + 256 * i;        // 0..1023
        uint32_t dstb = sb + 512 + b * LSTG;
        if (cidx < 512) {
            int mat = cidx >> 8;         // 0=Ehi 1=Elo
            int cc  = cidx & 255;
            int row = cc >> 2;
            int c16 = cc & 3;
            const __half* src = (mat == 0 ? g_Ehi : g_Elo)
                              + (size_t)(erow0 + row) * HDIM + ccol + c16 * 8;
            cpa16(dstb + mat * LMATE + row * ROWB + c16 * 16, src);
        } else {
            int cc  = cidx - 512;        // 0..511
            int row = cc >> 2;
            int c16 = cc & 3;
            const __half* src = g_WL + (size_t)(wrow0 + row) * HDIM + ccol + c16 * 8;
            cpa16(dstb + 2 * LMATE + row * ROWB + c16 * 16, src);
        }
    }
    CP_COMMIT();
}

__global__ __launch_bounds__(256, 2) void logodds_mma(
    const float* __restrict__ b_lin, float* __restrict__ out)
{
    const int kc  = blockIdx.y;
    const int beg = g_off_cat[kc];
    const int cnt = g_off_cat[kc + 1] - beg;
    const int m0  = blockIdx.x * LBM;
    if (m0 >= cnt) return;

    extern __shared__ char smem[];
    const uint32_t sb = smem_u32(smem);
    const int tid = threadIdx.x;
    const int w   = tid >> 5;
    const int l   = tid & 31;
    const int wm  = w >> 2;        // 0..1 (32 rows each)
    const int wn  = w & 3;         // 0..3 (32 cols each)

    if (tid < CCH)
        ((float*)smem)[tid] = b_lin[kc * CCH + tid];

    const int erow0 = beg + m0;
    const int wrow0 = kc * CCH;

    float acc[2][4][4];
#pragma unroll
    for (int a = 0; a < 2; a++)
#pragma unroll
        for (int b2 = 0; b2 < 4; b2++)
#pragma unroll
            for (int c = 0; c < 4; c++) acc[a][b2][c] = 0.f;

    load_stage_lo(tid, sb, 0, erow0, wrow0, 0);
    load_stage_lo(tid, sb, 1, erow0, wrow0, LBK);

    const int lr   = l & 15;
    const int lc16 = (l >> 4) << 4;

    for (int s = 0; s < LNST; s++) {
        const int b = s & 1;
        if (s < LNST - 1) cp_wait<1>(); else cp_wait<0>();
        __syncthreads();

        const uint32_t stg = sb + 512 + b * LSTG;
        const uint32_t eHi = stg, eLo = stg + LMATE, wB = stg + 2 * LMATE;

#pragma unroll
        for (int ks = 0; ks < 2; ks++) {
            const int kb = ks * 32 + lc16;
            uint32_t bb[2][4], af[2][4];
#pragma unroll
            for (int g2 = 0; g2 < 2; g2++) {
                uint32_t brow = wn * 32 + g2 * 16 + lr;
                ldm4(bb[g2], wB + brow * ROWB + kb);
            }
#pragma unroll
            for (int mi = 0; mi < 2; mi++) {
                uint32_t arow = wm * 32 + mi * 16 + lr;
                ldm4(af[mi], eHi + arow * ROWB + kb);
            }
#pragma unroll
            for (int mi = 0; mi < 2; mi++)
#pragma unroll
                for (int ni = 0; ni < 4; ni++)
                    mma16816(acc[mi][ni], af[mi], bb[ni >> 1][ni & 1], bb[ni >> 1][(ni & 1) + 2]);
#pragma unroll
            for (int mi = 0; mi < 2; mi++) {
                uint32_t arow = wm * 32 + mi * 16 + lr;
                ldm4(af[mi], eLo + arow * ROWB + kb);
            }
#pragma unroll
            for (int mi = 0; mi < 2; mi++)
#pragma unroll
                for (int ni = 0; ni < 4; ni++)
                    mma16816(acc[mi][ni], af[mi], bb[ni >> 1][ni & 1], bb[ni >> 1][(ni & 1) + 2]);
        }

        __syncthreads();
        if (s + 2 < LNST) load_stage_lo(tid, sb, b, erow0, wrow0, (s + 2) * LBK);
    }

    // epilogue: direct fragment writes (+bias) to out[t*CCH + col]
    {
        const float* bias = (const float*)smem;
#pragma unroll
        for (int mi = 0; mi < 2; mi++) {
            int r1 = wm * 32 + mi * 16 + (l >> 2);
            int r2 = r1 + 8;
            int m1 = m0 + r1, m2 = m0 + r2;
            int t1 = (m1 < cnt) ? g_perm_cat[beg + m1] : -1;
            int t2 = (m2 < cnt) ? g_perm_cat[beg + m2] : -1;
#pragma unroll
            for (int ni = 0; ni < 4; ni++) {
                int c0 = wn * 32 + ni * 8 + (l & 3) * 2;
                float b0 = bias[c0], b1 = bias[c0 + 1];
                if (t1 >= 0)
                    *(float2*)(out + (size_t)t1 * CCH + c0)
                        = make_float2(acc[mi][ni][0] + b0, acc[mi][ni][1] + b1);
                if (t2 >= 0)
                    *(float2*)(out + (size_t)t2 * CCH + c0)
                        = make_float2(acc[mi][ni][2] + b0, acc[mi][ni][3] + b1);
            }
        }
    }
}

// ---------------- launch ----------------
extern "C" void kernel_launch(void* const* d_in, const int* in_sizes, int n_in,
                              void* d_out, int out_size) {
    const float* et    = (const float*)d_in[0];
    const float* x     = (const float*)d_in[1];
    const float* h     = (const float*)d_in[2];
    const float* c     = (const float*)d_in[3];
    const int*   cat   = (const int*)d_in[4];
    const int*   ci    = (const int*)d_in[5];
    const float* W_lin = (const float*)d_in[6];
    const float* b_lin = (const float*)d_in[7];
    const float* W_ih  = (const float*)d_in[8];
    const float* W_hh  = (const float*)d_in[9];
    const float* b_ih  = (const float*)d_in[10];
    const float* b_hh  = (const float*)d_in[11];
    float* out = (float*)d_out;

    cudaFuncSetAttribute(gates_mma, cudaFuncAttributeMaxDynamicSharedMemorySize, SM_TOTAL);
    cudaFuncSetAttribute(logodds_mma, cudaFuncAttributeMaxDynamicSharedMemorySize, LSM_TOTAL);

    k_sort<<<1, 1024>>>(cat, ci);

    pack_W<<<MCI * GDIM, 128>>>(W_ih, W_hh);
    pack_WL<<<KCAT * CCH, 128>>>(W_lin);
    pack_A<<<NTOK, 128>>>(x, h);
    pack_E<<<NTOK, 128>>>(et);

    logodds_mma<<<dim3(3, KCAT), 256, LSM_TOTAL>>>(b_lin, out);

    gates_mma<<<dim3(NTOK / BM, GDIM / BN, MCI), 256, SM_TOTAL>>>(c, b_ih, b_hh, out);
}

// round 12
// speedup vs baseline: 4.2933x; 1.4345x over previous
#include <cuda_runtime.h>
#include <cuda_fp16.h>
#include <math.h>
#include <stdint.h>

// Problem constants
#define NTOK  4096
#define HDIM  512
#define CCH   128
#define KCAT  64
#define MCI   4
#define INDIM 1024
#define GDIM  2048      // 4*H
#define FDIM  1536      // INDIM + HDIM
#define APAD  4224      // NTOK + 128 tile slack

// gates GEMM tiling
#define BM 128
#define BN 128
#define BK 32
#define NSTAGES (FDIM / BK)     // 48
#define ROWB 80                 // padded row bytes (32 fp16 = 64B data + 16B pad)
#define MATB (BM * ROWB)        // 10240 bytes per matrix tile
#define STGB (2 * MATB)         // A, B   (20480)
#define SM_BIAS 512
#define SM_STG  1024
#define EPW 136                 // epilogue f32 row stride (floats)
#define SM_TOTAL (SM_STG + BM * EPW * 4)   // 70656 (covers 2*STGB=40960 stages too)

// logodds GEMM tiling (2-pass, unchanged)
#define LBM 64
#define LBN 128
#define LBK 32
#define LNST (HDIM / LBK)       // 16
#define LMATE (LBM * ROWB)      // 5120
#define LMATW (LBN * ROWB)      // 10240
#define LSTG  (2 * LMATE + LMATW)   // 20480
#define LSM_TOTAL (512 + 2 * LSTG)  // 41472

// ---------------- device scratch (static) ----------------
__device__ __half g_A[(size_t)APAD * FDIM];
__device__ __half g_W[(size_t)MCI * GDIM * FDIM];
__device__ __half g_Ehi[(size_t)APAD * HDIM];
__device__ __half g_Elo[(size_t)APAD * HDIM];
__device__ __half g_WL[(size_t)KCAT * CCH * HDIM];
__device__ int g_perm_ci[NTOK];
__device__ int g_perm_cat[NTOK];
__device__ int g_off_ci[MCI + 1];
__device__ int g_off_cat[KCAT + 1];

// ---------------- PTX helpers (sm_80-level only) ----------------
__device__ __forceinline__ uint32_t smem_u32(const void* p) {
    uint32_t a;
    asm("{ .reg .u64 t; cvta.to.shared.u64 t, %1; cvt.u32.u64 %0, t; }" : "=r"(a) : "l"(p));
    return a;
}
__device__ __forceinline__ void cpa16(uint32_t dst, const void* src) {
    asm volatile("cp.async.cg.shared.global [%0], [%1], 16;" :: "r"(dst), "l"(src));
}
#define CP_COMMIT() asm volatile("cp.async.commit_group;" ::: "memory")
template <int N> __device__ __forceinline__ void cp_wait() {
    asm volatile("cp.async.wait_group %0;" :: "n"(N) : "memory");
}
__device__ __forceinline__ void ldm4(uint32_t* r, uint32_t addr) {
    asm volatile("ldmatrix.sync.aligned.m8n8.x4.shared.b16 {%0,%1,%2,%3}, [%4];"
        : "=r"(r[0]), "=r"(r[1]), "=r"(r[2]), "=r"(r[3]) : "r"(addr));
}
__device__ __forceinline__ void mma16816(float* c, const uint32_t* a, uint32_t b0, uint32_t b1) {
    asm volatile(
        "mma.sync.aligned.m16n8k16.row.col.f32.f16.f16.f32 "
        "{%0,%1,%2,%3}, {%4,%5,%6,%7}, {%8,%9}, {%0,%1,%2,%3};"
        : "+f"(c[0]), "+f"(c[1]), "+f"(c[2]), "+f"(c[3])
        : "r"(a[0]), "r"(a[1]), "r"(a[2]), "r"(a[3]), "r"(b0), "r"(b1));
}

// ---------------- fused single-block counting sort ----------------
__global__ __launch_bounds__(1024) void k_sort(const int* __restrict__ cat,
                                               const int* __restrict__ ci) {
    __shared__ int s_ci[MCI], s_cat[KCAT], p_ci[MCI], p_cat[KCAT];
    const int tid = threadIdx.x;
    if (tid < MCI)  s_ci[tid]  = 0;
    if (tid < KCAT) s_cat[tid] = 0;
    __syncthreads();
    for (int n = tid; n < NTOK; n += 1024) {
        atomicAdd(&s_ci[ci[n]], 1);
        atomicAdd(&s_cat[cat[n]], 1);
    }
    __syncthreads();
    if (tid == 0) {
        int s = 0;
        for (int i = 0; i < MCI; i++) { g_off_ci[i] = s; p_ci[i] = s; s += s_ci[i]; }
        g_off_ci[MCI] = s;
    }
    if (tid == 32) {
        int s = 0;
        for (int i = 0; i < KCAT; i++) { g_off_cat[i] = s; p_cat[i] = s; s += s_cat[i]; }
        g_off_cat[KCAT] = s;
    }
    __syncthreads();
    for (int n = tid; n < NTOK; n += 1024) {
        g_perm_ci[atomicAdd(&p_ci[ci[n]], 1)] = n;
        g_perm_cat[atomicAdd(&p_cat[cat[n]], 1)] = n;
    }
}

// ---------------- pack activations: fp16 of permuted [x|h] ----------------
__global__ __launch_bounds__(128) void pack_A(const float* __restrict__ x,
                                              const float* __restrict__ h) {
    const int p = blockIdx.x;
    const int t = g_perm_ci[p];
    const int tid = threadIdx.x;
#pragma unroll
    for (int r = 0; r < 3; r++) {
        int col = (tid + 128 * r) * 4;
        float4 v = (col < INDIM)
                 ? *(const float4*)(x + (size_t)t * INDIM + col)
                 : *(const float4*)(h + (size_t)t * HDIM + (col - INDIM));
        float vv[4] = {v.x, v.y, v.z, v.w};
        ushort4 a4;
        unsigned short* ap = &a4.x;
#pragma unroll
        for (int j = 0; j < 4; j++)
            ap[j] = __half_as_ushort(__float2half_rn(vv[j]));
        *(ushort4*)(g_A + (size_t)p * FDIM + col) = a4;
    }
}

// ---------------- pack et: hi/lo fp16 in cat-perm order ----------------
__global__ __launch_bounds__(128) void pack_E(const float* __restrict__ et) {
    const int p = blockIdx.x;
    const int t = g_perm_cat[p];
    const int tid = threadIdx.x;
    int col = tid * 4;
    float4 v = *(const float4*)(et + (size_t)t * HDIM + col);
    float vv[4] = {v.x, v.y, v.z, v.w};
    ushort4 hi, lo;
    unsigned short* hp = &hi.x;
    unsigned short* lp = &lo.x;
#pragma unroll
    for (int j = 0; j < 4; j++) {
        __half hb = __float2half_rn(vv[j]);
        __half lb = __float2half_rn(vv[j] - __half2float(hb));
        hp[j] = __half_as_ushort(hb);
        lp[j] = __half_as_ushort(lb);
    }
    *(ushort4*)(g_Ehi + (size_t)p * HDIM + col) = hi;
    *(ushort4*)(g_Elo + (size_t)p * HDIM + col) = lo;
}

// ---------------- pack weights (fp16): row R = k*2048 + 4*u + gate ----------------
__global__ __launch_bounds__(128) void pack_W(const float* __restrict__ W_ih,
                                              const float* __restrict__ W_hh) {
    const int R = blockIdx.x;            // 0..8191
    const int k = R >> 11;
    const int r = R & 2047;
    const int u = r >> 2;
    const int gate = r & 3;
    const int g = gate * 512 + u;
    const int tid = threadIdx.x;
    const float* src_ih = W_ih + ((size_t)k * GDIM + g) * INDIM;
    const float* src_hh = W_hh + ((size_t)k * GDIM + g) * HDIM;
#pragma unroll
    for (int rr = 0; rr < 3; rr++) {
        int col = (tid + 128 * rr) * 4;
        float4 v = (col < INDIM) ? *(const float4*)(src_ih + col)
                                 : *(const float4*)(src_hh + (col - INDIM));
        float vv[4] = {v.x, v.y, v.z, v.w};
        ushort4 w4;
        unsigned short* wp = &w4.x;
#pragma unroll
        for (int j = 0; j < 4; j++)
            wp[j] = __half_as_ushort(__float2half_rn(vv[j]));
        *(ushort4*)(g_W + (size_t)R * FDIM + col) = w4;
    }
}

// ---------------- pack W_lin -> fp16 ----------------
__global__ __launch_bounds__(128) void pack_WL(const float* __restrict__ W_lin) {
    const int R = blockIdx.x;            // 0..8191 = kc*128 + cch
    const int tid = threadIdx.x;
    int col = tid * 4;
    float4 v = *(const float4*)(W_lin + (size_t)R * HDIM + col);
    float vv[4] = {v.x, v.y, v.z, v.w};
    ushort4 w4;
    unsigned short* wp = &w4.x;
#pragma unroll
    for (int j = 0; j < 4; j++)
        wp[j] = __half_as_ushort(__float2half_rn(vv[j]));
    *(ushort4*)(g_WL + (size_t)R * HDIM + col) = w4;
}

// ---------------- gates HMMA GEMM (fp16 single-pass) + fused LSTM epilogue ----------------
__device__ __forceinline__ void load_stage(int tid, uint32_t sb, int b,
                                           int arow0, int brow0, int ccol) {
#pragma unroll
    for (int i = 0; i < 4; i++) {
        int cidx = tid + 256 * i;        // 0..1023
        int mat  = cidx >> 9;            // 0=A 1=B
        int cc   = cidx & 511;
        int row  = cc >> 2;
        int c16  = cc & 3;
        uint32_t dst = sb + SM_STG + b * STGB + mat * MATB + row * ROWB + c16 * 16;
        const __half* src = (mat == 0)
            ? g_A + (size_t)(arow0 + row) * FDIM + ccol + c16 * 8
            : g_W + (size_t)(brow0 + row) * FDIM + ccol + c16 * 8;
        cpa16(dst, src);
    }
    CP_COMMIT();
}

__global__ __launch_bounds__(256, 2) void gates_mma(
    const float* __restrict__ c_in,
    const float* __restrict__ b_ih, const float* __restrict__ b_hh,
    float* __restrict__ out)
{
    const int k   = blockIdx.z;
    const int beg = g_off_ci[k];
    const int cnt = g_off_ci[k + 1] - beg;
    const int m0  = blockIdx.x * BM;
    if (m0 >= cnt) return;
    const int n0  = blockIdx.y * BN;

    extern __shared__ char smem[];
    const uint32_t sb = smem_u32(smem);
    const int tid = threadIdx.x;
    const int w   = tid >> 5;
    const int l   = tid & 31;
    const int wm  = w >> 2;
    const int wn  = w & 3;

    if (tid < 128) {
        int j = n0 + tid;
        int u = j >> 2, gate = j & 3;
        int g = gate * 512 + u;
        ((float*)(smem + SM_BIAS))[tid] = b_ih[k * GDIM + g] + b_hh[k * GDIM + g];
    }

    const int arow0 = beg + m0;
    const int brow0 = k * GDIM + n0;

    float acc[4][4][4];
#pragma unroll
    for (int a = 0; a < 4; a++)
#pragma unroll
        for (int b2 = 0; b2 < 4; b2++)
#pragma unroll
            for (int c = 0; c < 4; c++) acc[a][b2][c] = 0.f;

    load_stage(tid, sb, 0, arow0, brow0, 0);
    load_stage(tid, sb, 1, arow0, brow0, BK);

    const int lr   = l & 15;
    const int lc16 = (l >> 4) << 4;

    for (int s = 0; s < NSTAGES; s++) {
        const int b = s & 1;
        if (s < NSTAGES - 1) cp_wait<1>(); else cp_wait<0>();
        __syncthreads();

        const uint32_t stg = sb + SM_STG + b * STGB;
        const uint32_t aA = stg, bB = stg + MATB;

#pragma unroll
        for (int ks = 0; ks < 2; ks++) {
            const int kb = ks * 32 + lc16;
            uint32_t bb[2][4], af[4][4];
#pragma unroll
            for (int g2 = 0; g2 < 2; g2++) {
                uint32_t brow = wn * 32 + g2 * 16 + lr;
                ldm4(bb[g2], bB + brow * ROWB + kb);
            }
#pragma unroll
            for (int mi = 0; mi < 4; mi++) {
                uint32_t arow = wm * 64 + mi * 16 + lr;
                ldm4(af[mi], aA + arow * ROWB + kb);
            }
#pragma unroll
            for (int mi = 0; mi < 4; mi++)
#pragma unroll
                for (int ni = 0; ni < 4; ni++)
                    mma16816(acc[mi][ni], af[mi], bb[ni >> 1][ni & 1], bb[ni >> 1][(ni & 1) + 2]);
        }

        __syncthreads();
        if (s + 2 < NSTAGES) load_stage(tid, sb, b, arow0, brow0, (s + 2) * BK);
    }

    // -------- epilogue: acc -> smem f32 tile -> fused LSTM --------
    float* ep = (float*)(smem + SM_STG);
#pragma unroll
    for (int mi = 0; mi < 4; mi++)
#pragma unroll
        for (int ni = 0; ni < 4; ni++) {
            int r0 = wm * 64 + mi * 16 + (l >> 2);
            int c0 = wn * 32 + ni * 8 + (l & 3) * 2;
            *(float2*)&ep[r0 * EPW + c0]       = make_float2(acc[mi][ni][0], acc[mi][ni][1]);
            *(float2*)&ep[(r0 + 8) * EPW + c0] = make_float2(acc[mi][ni][2], acc[mi][ni][3]);
        }
    __syncthreads();

    {
        const float* bias = (const float*)(smem + SM_BIAS);
        const int row = tid >> 1;
        const int uu0 = (tid & 1) * 16;
        const int m = m0 + row;
        if (m < cnt) {
            const int t  = g_perm_ci[beg + m];
            const int u0 = n0 >> 2;
            const size_t OFF_H = (size_t)NTOK * CCH;
            const size_t OFF_C = OFF_H + (size_t)NTOK * HDIM;
#pragma unroll
            for (int j = 0; j < 16; j++) {
                int uu = uu0 + j;
                float4 v = *(const float4*)&ep[row * EPW + uu * 4];
                float iv = v.x + bias[4 * uu + 0];
                float fv = v.y + bias[4 * uu + 1];
                float gv = v.z + bias[4 * uu + 2];
                float ov = v.w + bias[4 * uu + 3];
                int u = u0 + uu;
                float cold = c_in[(size_t)t * HDIM + u];
                float si = 1.f / (1.f + expf(-iv));
                float sf = 1.f / (1.f + expf(-fv));
                float so = 1.f / (1.f + expf(-ov));
                float c2 = sf * cold + si * tanhf(gv);
                float h2 = so * tanhf(c2);
                out[OFF_H + (size_t)t * HDIM + u] = h2;
                out[OFF_C + (size_t)t * HDIM + u] = c2;
            }
        }
    }
}

// ---------------- logodds HMMA GEMM (fp16 2-pass) ----------------
__device__ __forceinline__ void load_stage_lo(int tid, uint32_t sb, int b,
                                              int erow0, int wrow0, int ccol) {
#pragma unroll
    for (int i = 0; i < 4; i++) {
        int cidx = tid + 256 * i;        // 0..1023
        uint32_t dstb = sb + 512 + b * LSTG;
        if (cidx < 512) {
            int mat = cidx >> 8;         // 0=Ehi 1=Elo
            int cc  = cidx & 255;
            int row = cc >> 2;
            int c16 = cc & 3;
            const __half* src = (mat == 0 ? g_Ehi : g_Elo)
                              + (size_t)(erow0 + row) * HDIM + ccol + c16 * 8;
            cpa16(dstb + mat * LMATE + row * ROWB + c16 * 16, src);
        } else {
            int cc  = cidx - 512;        // 0..511
            int row = cc >> 2;
            int c16 = cc & 3;
            const __half* src = g_WL + (size_t)(wrow0 + row) * HDIM + ccol + c16 * 8;
            cpa16(dstb + 2 * LMATE + row * ROWB + c16 * 16, src);
        }
    }
    CP_COMMIT();
}

__global__ __launch_bounds__(256, 2) void logodds_mma(
    const float* __restrict__ b_lin, float* __restrict__ out)
{
    const int kc  = blockIdx.y;
    const int beg = g_off_cat[kc];
    const int cnt = g_off_cat[kc + 1] - beg;
    const int m0  = blockIdx.x * LBM;
    if (m0 >= cnt) return;

    extern __shared__ char smem[];
    const uint32_t sb = smem_u32(smem);
    const int tid = threadIdx.x;
    const int w   = tid >> 5;
    const int l   = tid & 31;
    const int wm  = w >> 2;        // 0..1 (32 rows each)
    const int wn  = w & 3;         // 0..3 (32 cols each)

    if (tid < CCH)
        ((float*)smem)[tid] = b_lin[kc * CCH + tid];

    const int erow0 = beg + m0;
    const int wrow0 = kc * CCH;

    float acc[2][4][4];
#pragma unroll
    for (int a = 0; a < 2; a++)
#pragma unroll
        for (int b2 = 0; b2 < 4; b2++)
#pragma unroll
            for (int c = 0; c < 4; c++) acc[a][b2][c] = 0.f;

    load_stage_lo(tid, sb, 0, erow0, wrow0, 0);
    load_stage_lo(tid, sb, 1, erow0, wrow0, LBK);

    const int lr   = l & 15;
    const int lc16 = (l >> 4) << 4;

    for (int s = 0; s < LNST; s++) {
        const int b = s & 1;
        if (s < LNST - 1) cp_wait<1>(); else cp_wait<0>();
        __syncthreads();

        const uint32_t stg = sb + 512 + b * LSTG;
        const uint32_t eHi = stg, eLo = stg + LMATE, wB = stg + 2 * LMATE;

#pragma unroll
        for (int ks = 0; ks < 2; ks++) {
            const int kb = ks * 32 + lc16;
            uint32_t bb[2][4], af[2][4];
#pragma unroll
            for (int g2 = 0; g2 < 2; g2++) {
                uint32_t brow = wn * 32 + g2 * 16 + lr;
                ldm4(bb[g2], wB + brow * ROWB + kb);
            }
#pragma unroll
            for (int mi = 0; mi < 2; mi++) {
                uint32_t arow = wm * 32 + mi * 16 + lr;
                ldm4(af[mi], eHi + arow * ROWB + kb);
            }
#pragma unroll
            for (int mi = 0; mi < 2; mi++)
#pragma unroll
                for (int ni = 0; ni < 4; ni++)
                    mma16816(acc[mi][ni], af[mi], bb[ni >> 1][ni & 1], bb[ni >> 1][(ni & 1) + 2]);
#pragma unroll
            for (int mi = 0; mi < 2; mi++) {
                uint32_t arow = wm * 32 + mi * 16 + lr;
                ldm4(af[mi], eLo + arow * ROWB + kb);
            }
#pragma unroll
            for (int mi = 0; mi < 2; mi++)
#pragma unroll
                for (int ni = 0; ni < 4; ni++)
                    mma16816(acc[mi][ni], af[mi], bb[ni >> 1][ni & 1], bb[ni >> 1][(ni & 1) + 2]);
        }

        __syncthreads();
        if (s + 2 < LNST) load_stage_lo(tid, sb, b, erow0, wrow0, (s + 2) * LBK);
    }

    // epilogue: direct fragment writes (+bias) to out[t*CCH + col]
    {
        const float* bias = (const float*)smem;
#pragma unroll
        for (int mi = 0; mi < 2; mi++) {
            int r1 = wm * 32 + mi * 16 + (l >> 2);
            int r2 = r1 + 8;
            int m1 = m0 + r1, m2 = m0 + r2;
            int t1 = (m1 < cnt) ? g_perm_cat[beg + m1] : -1;
            int t2 = (m2 < cnt) ? g_perm_cat[beg + m2] : -1;
#pragma unroll
            for (int ni = 0; ni < 4; ni++) {
                int c0 = wn * 32 + ni * 8 + (l & 3) * 2;
                float b0 = bias[c0], b1 = bias[c0 + 1];
                if (t1 >= 0)
                    *(float2*)(out + (size_t)t1 * CCH + c0)
                        = make_float2(acc[mi][ni][0] + b0, acc[mi][ni][1] + b1);
                if (t2 >= 0)
                    *(float2*)(out + (size_t)t2 * CCH + c0)
                        = make_float2(acc[mi][ni][2] + b0, acc[mi][ni][3] + b1);
            }
        }
    }
}

// ---------------- launch ----------------
extern "C" void kernel_launch(void* const* d_in, const int* in_sizes, int n_in,
                              void* d_out, int out_size) {
    const float* et    = (const float*)d_in[0];
    const float* x     = (const float*)d_in[1];
    const float* h     = (const float*)d_in[2];
    const float* c     = (const float*)d_in[3];
    const int*   cat   = (const int*)d_in[4];
    const int*   ci    = (const int*)d_in[5];
    const float* W_lin = (const float*)d_in[6];
    const float* b_lin = (const float*)d_in[7];
    const float* W_ih  = (const float*)d_in[8];
    const float* W_hh  = (const float*)d_in[9];
    const float* b_ih  = (const float*)d_in[10];
    const float* b_hh  = (const float*)d_in[11];
    float* out = (float*)d_out;

    cudaFuncSetAttribute(gates_mma, cudaFuncAttributeMaxDynamicSharedMemorySize, SM_TOTAL);
    cudaFuncSetAttribute(logodds_mma, cudaFuncAttributeMaxDynamicSharedMemorySize, LSM_TOTAL);

    k_sort<<<1, 1024>>>(cat, ci);

    pack_W<<<MCI * GDIM, 128>>>(W_ih, W_hh);
    pack_WL<<<KCAT * CCH, 128>>>(W_lin);
    pack_A<<<NTOK, 128>>>(x, h);
    pack_E<<<NTOK, 128>>>(et);

    logodds_mma<<<dim3(3, KCAT), 256, LSM_TOTAL>>>(b_lin, out);

    gates_mma<<<dim3(NTOK / BM, GDIM / BN, MCI), 256, SM_TOTAL>>>(c, b_ih, b_hh, out);
}

// round 14
// speedup vs baseline: 4.6978x; 1.0942x over previous
#include <cuda_runtime.h>
#include <cuda_fp16.h>
#include <math.h>
#include <stdint.h>

// Problem constants
#define NTOK  4096
#define HDIM  512
#define CCH   128
#define KCAT  64
#define MCI   4
#define INDIM 1024
#define GDIM  2048      // 4*H
#define FDIM  1536      // INDIM + HDIM
#define APAD  4224      // NTOK + 128 tile slack

// gates GEMM tiling
#define BM 128
#define BN 128
#define BK 64
#define NSTAGES (FDIM / BK)     // 24
#define NBUF 3
#define ROWB 144                // 64 fp16 = 128B data + 16B pad
#define MATB (BM * ROWB)        // 18432
#define STGB (2 * MATB)         // A + B = 36864
#define SM_BIAS 512
#define SM_STG  1024
#define EPW 136                 // epilogue f32 row stride (floats)
#define SM_TOTAL (SM_STG + NBUF * STGB)   // 111616 (epilogue 69632 reuses stages)

// logodds GEMM tiling (2-pass, unchanged, ROWB=80 layout)
#define LROWB 80
#define LBM 64
#define LBK 32
#define LNST (HDIM / LBK)       // 16
#define LMATE (LBM * LROWB)     // 5120
#define LMATW (CCH * LROWB)     // 10240
#define LSTG  (2 * LMATE + LMATW)   // 20480
#define LSM_TOTAL (512 + 2 * LSTG)  // 41472

// ---------------- device scratch (static) ----------------
__device__ __half g_A[(size_t)APAD * FDIM];
__device__ __half g_W[(size_t)MCI * GDIM * FDIM];
__device__ __half g_Ehi[(size_t)APAD * HDIM];
__device__ __half g_Elo[(size_t)APAD * HDIM];
__device__ __half g_WL[(size_t)KCAT * CCH * HDIM];
__device__ int g_perm_ci[NTOK];
__device__ int g_perm_cat[NTOK];
__device__ int g_off_ci[MCI + 1];
__device__ int g_off_cat[KCAT + 1];

// ---------------- PTX helpers (sm_80-level only) ----------------
__device__ __forceinline__ uint32_t smem_u32(const void* p) {
    uint32_t a;
    asm("{ .reg .u64 t; cvta.to.shared.u64 t, %1; cvt.u32.u64 %0, t; }" : "=r"(a) : "l"(p));
    return a;
}
__device__ __forceinline__ void cpa16(uint32_t dst, const void* src) {
    asm volatile("cp.async.cg.shared.global [%0], [%1], 16;" :: "r"(dst), "l"(src));
}
#define CP_COMMIT() asm volatile("cp.async.commit_group;" ::: "memory")
template <int N> __device__ __forceinline__ void cp_wait() {
    asm volatile("cp.async.wait_group %0;" :: "n"(N) : "memory");
}
__device__ __forceinline__ void ldm4(uint32_t* r, uint32_t addr) {
    asm volatile("ldmatrix.sync.aligned.m8n8.x4.shared.b16 {%0,%1,%2,%3}, [%4];"
        : "=r"(r[0]), "=r"(r[1]), "=r"(r[2]), "=r"(r[3]) : "r"(addr));
}
__device__ __forceinline__ void mma16816(float* c, const uint32_t* a, uint32_t b0, uint32_t b1) {
    asm volatile(
        "mma.sync.aligned.m16n8k16.row.col.f32.f16.f16.f32 "
        "{%0,%1,%2,%3}, {%4,%5,%6,%7}, {%8,%9}, {%0,%1,%2,%3};"
        : "+f"(c[0]), "+f"(c[1]), "+f"(c[2]), "+f"(c[3])
        : "r"(a[0]), "r"(a[1]), "r"(a[2]), "r"(a[3]), "r"(b0), "r"(b1));
}

// ---------------- fused single-block counting sort ----------------
__global__ __launch_bounds__(1024) void k_sort(const int* __restrict__ cat,
                                               const int* __restrict__ ci) {
    __shared__ int s_ci[MCI], s_cat[KCAT], p_ci[MCI], p_cat[KCAT];
    const int tid = threadIdx.x;
    if (tid < MCI)  s_ci[tid]  = 0;
    if (tid < KCAT) s_cat[tid] = 0;
    __syncthreads();
    for (int n = tid; n < NTOK; n += 1024) {
        atomicAdd(&s_ci[ci[n]], 1);
        atomicAdd(&s_cat[cat[n]], 1);
    }
    __syncthreads();
    if (tid == 0) {
        int s = 0;
        for (int i = 0; i < MCI; i++) { g_off_ci[i] = s; p_ci[i] = s; s += s_ci[i]; }
        g_off_ci[MCI] = s;
    }
    if (tid == 32) {
        int s = 0;
        for (int i = 0; i < KCAT; i++) { g_off_cat[i] = s; p_cat[i] = s; s += s_cat[i]; }
        g_off_cat[KCAT] = s;
    }
    __syncthreads();
    for (int n = tid; n < NTOK; n += 1024) {
        g_perm_ci[atomicAdd(&p_ci[ci[n]], 1)] = n;
        g_perm_cat[atomicAdd(&p_cat[cat[n]], 1)] = n;
    }
}

// ---------------- merged activation pack: A (ci-perm fp16) + E (cat-perm hi/lo) ----------------
__global__ __launch_bounds__(128) void pack_act(const float* __restrict__ x,
                                                const float* __restrict__ h,
                                                const float* __restrict__ et) {
    const int p = blockIdx.x;
    const int tid = threadIdx.x;
    // --- A part: [x|h][perm_ci[p]] -> fp16 ---
    {
        const int t = g_perm_ci[p];
#pragma unroll
        for (int r = 0; r < 3; r++) {
            int col = (tid + 128 * r) * 4;
            float4 v = (col < INDIM)
                     ? *(const float4*)(x + (size_t)t * INDIM + col)
                     : *(const float4*)(h + (size_t)t * HDIM + (col - INDIM));
            float vv[4] = {v.x, v.y, v.z, v.w};
            ushort4 a4;
            unsigned short* ap = &a4.x;
#pragma unroll
            for (int j = 0; j < 4; j++)
                ap[j] = __half_as_ushort(__float2half_rn(vv[j]));
            *(ushort4*)(g_A + (size_t)p * FDIM + col) = a4;
        }
    }
    // --- E part: et[perm_cat[p]] -> hi/lo fp16 ---
    {
        const int t = g_perm_cat[p];
        int col = tid * 4;
        float4 v = *(const float4*)(et + (size_t)t * HDIM + col);
        float vv[4] = {v.x, v.y, v.z, v.w};
        ushort4 hi, lo;
        unsigned short* hp = &hi.x;
        unsigned short* lp = &lo.x;
#pragma unroll
        for (int j = 0; j < 4; j++) {
            __half hb = __float2half_rn(vv[j]);
            __half lb = __float2half_rn(vv[j] - __half2float(hb));
            hp[j] = __half_as_ushort(hb);
            lp[j] = __half_as_ushort(lb);
        }
        *(ushort4*)(g_Ehi + (size_t)p * HDIM + col) = hi;
        *(ushort4*)(g_Elo + (size_t)p * HDIM + col) = lo;
    }
}

// ---------------- merged weight pack: W (interleaved fp16) + WL (fp16) ----------------
__global__ __launch_bounds__(128) void pack_w_all(const float* __restrict__ W_ih,
                                                  const float* __restrict__ W_hh,
                                                  const float* __restrict__ W_lin) {
    const int tid = threadIdx.x;
    if (blockIdx.x < MCI * GDIM) {
        const int R = blockIdx.x;            // 0..8191
        const int k = R >> 11;
        const int r = R & 2047;
        const int u = r >> 2;
        const int gate = r & 3;
        const int g = gate * 512 + u;
        const float* src_ih = W_ih + ((size_t)k * GDIM + g) * INDIM;
        const float* src_hh = W_hh + ((size_t)k * GDIM + g) * HDIM;
#pragma unroll
        for (int rr = 0; rr < 3; rr++) {
            int col = (tid + 128 * rr) * 4;
            float4 v = (col < INDIM) ? *(const float4*)(src_ih + col)
                                     : *(const float4*)(src_hh + (col - INDIM));
            float vv[4] = {v.x, v.y, v.z, v.w};
            ushort4 w4;
            unsigned short* wp = &w4.x;
#pragma unroll
            for (int j = 0; j < 4; j++)
                wp[j] = __half_as_ushort(__float2half_rn(vv[j]));
            *(ushort4*)(g_W + (size_t)R * FDIM + col) = w4;
        }
    } else {
        const int R = blockIdx.x - MCI * GDIM;   // 0..8191 = kc*128 + cch
        int col = tid * 4;
        float4 v = *(const float4*)(W_lin + (size_t)R * HDIM + col);
        float vv[4] = {v.x, v.y, v.z, v.w};
        ushort4 w4;
        unsigned short* wp = &w4.x;
#pragma unroll
        for (int j = 0; j < 4; j++)
            wp[j] = __half_as_ushort(__float2half_rn(vv[j]));
        *(ushort4*)(g_WL + (size_t)R * HDIM + col) = w4;
    }
}

// ---------------- gates HMMA GEMM (fp16, BK=64, 3-stage pipeline) ----------------
__device__ __forceinline__ void load_stage(int tid, uint32_t sb, int b,
                                           int arow0, int brow0, int ccol) {
#pragma unroll
    for (int i = 0; i < 8; i++) {
        int cidx = tid + 256 * i;        // 0..2047
        int mat  = cidx >> 10;           // 0=A 1=B
        int cc   = cidx & 1023;
        int row  = cc >> 3;              // 0..127
        int c16  = cc & 7;               // 8 x 16B = 128B per row
        uint32_t dst = sb + SM_STG + b * STGB + mat * MATB + row * ROWB + c16 * 16;
        const __half* src = (mat == 0)
            ? g_A + (size_t)(arow0 + row) * FDIM + ccol + c16 * 8
            : g_W + (size_t)(brow0 + row) * FDIM + ccol + c16 * 8;
        cpa16(dst, src);
    }
    CP_COMMIT();
}

__global__ __launch_bounds__(256, 2) void gates_mma(
    const float* __restrict__ c_in,
    const float* __restrict__ b_ih, const float* __restrict__ b_hh,
    float* __restrict__ out)
{
    const int k   = blockIdx.z;
    const int beg = g_off_ci[k];
    const int cnt = g_off_ci[k + 1] - beg;
    const int m0  = blockIdx.x * BM;
    if (m0 >= cnt) return;
    const int n0  = blockIdx.y * BN;

    extern __shared__ char smem[];
    const uint32_t sb = smem_u32(smem);
    const int tid = threadIdx.x;
    const int w   = tid >> 5;
    const int l   = tid & 31;
    const int wm  = w >> 2;
    const int wn  = w & 3;

    if (tid < 128) {
        int j = n0 + tid;
        int u = j >> 2, gate = j & 3;
        int g = gate * 512 + u;
        ((float*)(smem + SM_BIAS))[tid] = b_ih[k * GDIM + g] + b_hh[k * GDIM + g];
    }

    const int arow0 = beg + m0;
    const int brow0 = k * GDIM + n0;

    float acc[4][4][4];
#pragma unroll
    for (int a = 0; a < 4; a++)
#pragma unroll
        for (int b2 = 0; b2 < 4; b2++)
#pragma unroll
            for (int c = 0; c < 4; c++) acc[a][b2][c] = 0.f;

    load_stage(tid, sb, 0, arow0, brow0, 0);
    load_stage(tid, sb, 1, arow0, brow0, BK);
    load_stage(tid, sb, 2, arow0, brow0, 2 * BK);

    const int lr   = l & 15;
    const int lc16 = (l >> 4) << 4;

    int b = 0;
    for (int s = 0; s < NSTAGES; s++) {
        if (s <= NSTAGES - 3)      cp_wait<2>();
        else if (s == NSTAGES - 2) cp_wait<1>();
        else                       cp_wait<0>();
        __syncthreads();

        const uint32_t stg = sb + SM_STG + b * STGB;
        const uint32_t aA = stg, bB = stg + MATB;

#pragma unroll
        for (int ks = 0; ks < 4; ks++) {
            const int kb = ks * 32 + lc16;
            uint32_t bb[2][4], af[4][4];
#pragma unroll
            for (int g2 = 0; g2 < 2; g2++) {
                uint32_t brow = wn * 32 + g2 * 16 + lr;
                ldm4(bb[g2], bB + brow * ROWB + kb);
            }
#pragma unroll
            for (int mi = 0; mi < 4; mi++) {
                uint32_t arow = wm * 64 + mi * 16 + lr;
                ldm4(af[mi], aA + arow * ROWB + kb);
            }
#pragma unroll
            for (int mi = 0; mi < 4; mi++)
#pragma unroll
                for (int ni = 0; ni < 4; ni++)
                    mma16816(acc[mi][ni], af[mi], bb[ni >> 1][ni & 1], bb[ni >> 1][(ni & 1) + 2]);
        }

        __syncthreads();
        if (s + 3 < NSTAGES) load_stage(tid, sb, b, arow0, brow0, (s + 3) * BK);
        b = (b == NBUF - 1) ? 0 : b + 1;
    }

    // -------- epilogue: acc -> smem f32 tile -> fused LSTM --------
    float* ep = (float*)(smem + SM_STG);
#pragma unroll
    for (int mi = 0; mi < 4; mi++)
#pragma unroll
        for (int ni = 0; ni < 4; ni++) {
            int r0 = wm * 64 + mi * 16 + (l >> 2);
            int c0 = wn * 32 + ni * 8 + (l & 3) * 2;
            *(float2*)&ep[r0 * EPW + c0]       = make_float2(acc[mi][ni][0], acc[mi][ni][1]);
            *(float2*)&ep[(r0 + 8) * EPW + c0] = make_float2(acc[mi][ni][2], acc[mi][ni][3]);
        }
    __syncthreads();

    {
        const float* bias = (const float*)(smem + SM_BIAS);
        const int row = tid >> 1;
        const int uu0 = (tid & 1) * 16;
        const int m = m0 + row;
        if (m < cnt) {
            const int t  = g_perm_ci[beg + m];
            const int u0 = n0 >> 2;
            const size_t OFF_H = (size_t)NTOK * CCH;
            const size_t OFF_C = OFF_H + (size_t)NTOK * HDIM;
#pragma unroll
            for (int j = 0; j < 16; j++) {
                int uu = uu0 + j;
                float4 v = *(const float4*)&ep[row * EPW + uu * 4];
                float iv = v.x + bias[4 * uu + 0];
                float fv = v.y + bias[4 * uu + 1];
                float gv = v.z + bias[4 * uu + 2];
                float ov = v.w + bias[4 * uu + 3];
                int u = u0 + uu;
                float cold = c_in[(size_t)t * HDIM + u];
                float si = 1.f / (1.f + expf(-iv));
                float sf = 1.f / (1.f + expf(-fv));
                float so = 1.f / (1.f + expf(-ov));
                float c2 = sf * cold + si * tanhf(gv);
                float h2 = so * tanhf(c2);
                out[OFF_H + (size_t)t * HDIM + u] = h2;
                out[OFF_C + (size_t)t * HDIM + u] = c2;
            }
        }
    }
}

// ---------------- logodds HMMA GEMM (fp16 2-pass, unchanged) ----------------
__device__ __forceinline__ void load_stage_lo(int tid, uint32_t sb, int b,
                                              int erow0, int wrow0, int ccol) {
#pragma unroll
    for (int i = 0; i < 4; i++) {
        int cidx = tid + 256 * i;        // 0..1023
        uint32_t dstb = sb + 512 + b * LSTG;
        if (cidx < 512) {
            int mat = cidx >> 8;         // 0=Ehi 1=Elo
            int cc  = cidx & 255;
            int row = cc >> 2;
            int c16 = cc & 3;
            const __half* src = (mat == 0 ? g_Ehi : g_Elo)
                              + (size_t)(erow0 + row) * HDIM + ccol + c16 * 8;
            cpa16(dstb + mat * LMATE + row * LROWB + c16 * 16, src);
        } else {
            int cc  = cidx - 512;        // 0..511
            int row = cc >> 2;
            int c16 = cc & 3;
            const __half* src = g_WL + (size_t)(wrow0 + row) * HDIM + ccol + c16 * 8;
            cpa16(dstb + 2 * LMATE + row * LROWB + c16 * 16, src);
        }
    }
    CP_COMMIT();
}

__global__ __launch_bounds__(256, 2) void logodds_mma(
    const float* __restrict__ b_lin, float* __restrict__ out)
{
    const int kc  = blockIdx.y;
    const int beg = g_off_cat[kc];
    const int cnt = g_off_cat[kc + 1] - beg;
    const int m0  = blockIdx.x * LBM;
    if (m0 >= cnt) return;

    extern __shared__ char smem[];
    const uint32_t sb = smem_u32(smem);
    const int tid = threadIdx.x;
    const int w   = tid >> 5;
    const int l   = tid & 31;
    const int wm  = w >> 2;
    const int wn  = w & 3;

    if (tid < CCH)
        ((float*)smem)[tid] = b_lin[kc * CCH + tid];

    const int erow0 = beg + m0;
    const int wrow0 = kc * CCH;

    float acc[2][4][4];
#pragma unroll
    for (int a = 0; a < 2; a++)
#pragma unroll
        for (int b2 = 0; b2 < 4; b2++)
#pragma unroll
            for (int c = 0; c < 4; c++) acc[a][b2][c] = 0.f;

    load_stage_lo(tid, sb, 0, erow0, wrow0, 0);
    load_stage_lo(tid, sb, 1, erow0, wrow0, LBK);

    const int lr   = l & 15;
    const int lc16 = (l >> 4) << 4;

    for (int s = 0; s < LNST; s++) {
        const int b = s & 1;
        if (s < LNST - 1) cp_wait<1>(); else cp_wait<0>();
        __syncthreads();

        const uint32_t stg = sb + 512 + b * LSTG;
        const uint32_t eHi = stg, eLo = stg + LMATE, wB = stg + 2 * LMATE;

#pragma unroll
        for (int ks = 0; ks < 2; ks++) {
            const int kb = ks * 32 + lc16;
            uint32_t bb[2][4], af[2][4];
#pragma unroll
            for (int g2 = 0; g2 < 2; g2++) {
                uint32_t brow = wn * 32 + g2 * 16 + lr;
                ldm4(bb[g2], wB + brow * LROWB + kb);
            }
#pragma unroll
            for (int mi = 0; mi < 2; mi++) {
                uint32_t arow = wm * 32 + mi * 16 + lr;
                ldm4(af[mi], eHi + arow * LROWB + kb);
            }
#pragma unroll
            for (int mi = 0; mi < 2; mi++)
#pragma unroll
                for (int ni = 0; ni < 4; ni++)
                    mma16816(acc[mi][ni], af[mi], bb[ni >> 1][ni & 1], bb[ni >> 1][(ni & 1) + 2]);
#pragma unroll
            for (int mi = 0; mi < 2; mi++) {
                uint32_t arow = wm * 32 + mi * 16 + lr;
                ldm4(af[mi], eLo + arow * LROWB + kb);
            }
#pragma unroll
            for (int mi = 0; mi < 2; mi++)
#pragma unroll
                for (int ni = 0; ni < 4; ni++)
                    mma16816(acc[mi][ni], af[mi], bb[ni >> 1][ni & 1], bb[ni >> 1][(ni & 1) + 2]);
        }

        __syncthreads();
        if (s + 2 < LNST) load_stage_lo(tid, sb, b, erow0, wrow0, (s + 2) * LBK);
    }

    {
        const float* bias = (const float*)smem;
#pragma unroll
        for (int mi = 0; mi < 2; mi++) {
            int r1 = wm * 32 + mi * 16 + (l >> 2);
            int r2 = r1 + 8;
            int m1 = m0 + r1, m2 = m0 + r2;
            int t1 = (m1 < cnt) ? g_perm_cat[beg + m1] : -1;
            int t2 = (m2 < cnt) ? g_perm_cat[beg + m2] : -1;
#pragma unroll
            for (int ni = 0; ni < 4; ni++) {
                int c0 = wn * 32 + ni * 8 + (l & 3) * 2;
                float b0 = bias[c0], b1 = bias[c0 + 1];
                if (t1 >= 0)
                    *(float2*)(out + (size_t)t1 * CCH + c0)
                        = make_float2(acc[mi][ni][0] + b0, acc[mi][ni][1] + b1);
                if (t2 >= 0)
                    *(float2*)(out + (size_t)t2 * CCH + c0)
                        = make_float2(acc[mi][ni][2] + b0, acc[mi][ni][3] + b1);
            }
        }
    }
}

// ---------------- launch ----------------
extern "C" void kernel_launch(void* const* d_in, const int* in_sizes, int n_in,
                              void* d_out, int out_size) {
    const float* et    = (const float*)d_in[0];
    const float* x     = (const float*)d_in[1];
    const float* h     = (const float*)d_in[2];
    const float* c     = (const float*)d_in[3];
    const int*   cat   = (const int*)d_in[4];
    const int*   ci    = (const int*)d_in[5];
    const float* W_lin = (const float*)d_in[6];
    const float* b_lin = (const float*)d_in[7];
    const float* W_ih  = (const float*)d_in[8];
    const float* W_hh  = (const float*)d_in[9];
    const float* b_ih  = (const float*)d_in[10];
    const float* b_hh  = (const float*)d_in[11];
    float* out = (float*)d_out;

    cudaFuncSetAttribute(gates_mma, cudaFuncAttributeMaxDynamicSharedMemorySize, SM_TOTAL);
    cudaFuncSetAttribute(logodds_mma, cudaFuncAttributeMaxDynamicSharedMemorySize, LSM_TOTAL);

    k_sort<<<1, 1024>>>(cat, ci);

    pack_w_all<<<MCI * GDIM + KCAT * CCH, 128>>>(W_ih, W_hh, W_lin);
    pack_act<<<NTOK, 128>>>(x, h, et);

    logodds_mma<<<dim3(3, KCAT), 256, LSM_TOTAL>>>(b_lin, out);

    gates_mma<<<dim3(NTOK / BM, GDIM / BN, MCI), 256, SM_TOTAL>>>(c, b_ih, b_hh, out);
}

// round 15
// speedup vs baseline: 5.6204x; 1.1964x over previous
#include <cuda_runtime.h>
#include <cuda_fp16.h>
#include <math.h>
#include <stdint.h>

// Problem constants
#define NTOK  4096
#define HDIM  512
#define CCH   128
#define KCAT  64
#define MCI   4
#define INDIM 1024
#define GDIM  2048      // 4*H
#define FDIM  1536      // INDIM + HDIM
#define APAD  4224      // NTOK + 128 tile slack

// gates GEMM tiling
#define BM 128
#define BN 128
#define BK 64
#define NSTAGES (FDIM / BK)     // 24
#define NBUF 3
#define ROWB 144                // 64 fp16 = 128B data + 16B pad
#define MATB (BM * ROWB)        // 18432
#define STGB (2 * MATB)         // 36864
#define SM_BIAS 512
#define SM_STG  1024
#define EPW 136                 // epilogue f32 row stride (floats)
#define SM_TOTAL (SM_STG + NBUF * STGB)   // 111616

// logodds tiling (single-pass fp16, LBK=64, 3-buf) — fits inside SM_TOTAL
#define LBM 64
#define LBK 64
#define LNST (HDIM / LBK)       // 8
#define LMATE (LBM * ROWB)      // 9216
#define LMATW (CCH * ROWB)      // 18432
#define LSTG  (LMATE + LMATW)   // 27648 ; 3 bufs = 82944 < 110592

// ---------------- device scratch (static) ----------------
__device__ __half g_A[(size_t)APAD * FDIM];
__device__ __half g_W[(size_t)MCI * GDIM * FDIM];
__device__ __half g_E[(size_t)APAD * HDIM];
__device__ __half g_WL[(size_t)KCAT * CCH * HDIM];
__device__ int g_perm_ci[NTOK];
__device__ int g_perm_cat[NTOK];
__device__ int g_off_ci[MCI + 1];
__device__ int g_off_cat[KCAT + 1];

// ---------------- PTX helpers (sm_80-level only) ----------------
__device__ __forceinline__ uint32_t smem_u32(const void* p) {
    uint32_t a;
    asm("{ .reg .u64 t; cvta.to.shared.u64 t, %1; cvt.u32.u64 %0, t; }" : "=r"(a) : "l"(p));
    return a;
}
__device__ __forceinline__ void cpa16(uint32_t dst, const void* src) {
    asm volatile("cp.async.cg.shared.global [%0], [%1], 16;" :: "r"(dst), "l"(src));
}
#define CP_COMMIT() asm volatile("cp.async.commit_group;" ::: "memory")
template <int N> __device__ __forceinline__ void cp_wait() {
    asm volatile("cp.async.wait_group %0;" :: "n"(N) : "memory");
}
__device__ __forceinline__ void ldm4(uint32_t* r, uint32_t addr) {
    asm volatile("ldmatrix.sync.aligned.m8n8.x4.shared.b16 {%0,%1,%2,%3}, [%4];"
        : "=r"(r[0]), "=r"(r[1]), "=r"(r[2]), "=r"(r[3]) : "r"(addr));
}
__device__ __forceinline__ void mma16816(float* c, const uint32_t* a, uint32_t b0, uint32_t b1) {
    asm volatile(
        "mma.sync.aligned.m16n8k16.row.col.f32.f16.f16.f32 "
        "{%0,%1,%2,%3}, {%4,%5,%6,%7}, {%8,%9}, {%0,%1,%2,%3};"
        : "+f"(c[0]), "+f"(c[1]), "+f"(c[2]), "+f"(c[3])
        : "r"(a[0]), "r"(a[1]), "r"(a[2]), "r"(a[3]), "r"(b0), "r"(b1));
}

// ---------------- fused single-block counting sort ----------------
__global__ __launch_bounds__(1024) void k_sort(const int* __restrict__ cat,
                                               const int* __restrict__ ci) {
    __shared__ int s_ci[MCI], s_cat[KCAT], p_ci[MCI], p_cat[KCAT];
    const int tid = threadIdx.x;
    if (tid < MCI)  s_ci[tid]  = 0;
    if (tid < KCAT) s_cat[tid] = 0;
    __syncthreads();
    for (int n = tid; n < NTOK; n += 1024) {
        atomicAdd(&s_ci[ci[n]], 1);
        atomicAdd(&s_cat[cat[n]], 1);
    }
    __syncthreads();
    if (tid == 0) {
        int s = 0;
        for (int i = 0; i < MCI; i++) { g_off_ci[i] = s; p_ci[i] = s; s += s_ci[i]; }
        g_off_ci[MCI] = s;
    }
    if (tid == 32) {
        int s = 0;
        for (int i = 0; i < KCAT; i++) { g_off_cat[i] = s; p_cat[i] = s; s += s_cat[i]; }
        g_off_cat[KCAT] = s;
    }
    __syncthreads();
    for (int n = tid; n < NTOK; n += 1024) {
        g_perm_ci[atomicAdd(&p_ci[ci[n]], 1)] = n;
        g_perm_cat[atomicAdd(&p_cat[cat[n]], 1)] = n;
    }
}

// ---------------- merged pack: weights (W + WL) and activations (A + E) ----------------
__global__ __launch_bounds__(128) void pack_all(const float* __restrict__ W_ih,
                                                const float* __restrict__ W_hh,
                                                const float* __restrict__ W_lin,
                                                const float* __restrict__ x,
                                                const float* __restrict__ h,
                                                const float* __restrict__ et) {
    const int tid = threadIdx.x;
    const int bid = blockIdx.x;
    if (bid < MCI * GDIM) {
        // gates weights, i-f-g-o interleaved rows
        const int R = bid;
        const int k = R >> 11;
        const int r = R & 2047;
        const int u = r >> 2;
        const int gate = r & 3;
        const int g = gate * 512 + u;
        const float* src_ih = W_ih + ((size_t)k * GDIM + g) * INDIM;
        const float* src_hh = W_hh + ((size_t)k * GDIM + g) * HDIM;
#pragma unroll
        for (int rr = 0; rr < 3; rr++) {
            int col = (tid + 128 * rr) * 4;
            float4 v = (col < INDIM) ? *(const float4*)(src_ih + col)
                                     : *(const float4*)(src_hh + (col - INDIM));
            float vv[4] = {v.x, v.y, v.z, v.w};
            ushort4 w4;
            unsigned short* wp = &w4.x;
#pragma unroll
            for (int j = 0; j < 4; j++)
                wp[j] = __half_as_ushort(__float2half_rn(vv[j]));
            *(ushort4*)(g_W + (size_t)R * FDIM + col) = w4;
        }
    } else if (bid < MCI * GDIM + KCAT * CCH) {
        // W_lin -> fp16
        const int R = bid - MCI * GDIM;
        int col = tid * 4;
        float4 v = *(const float4*)(W_lin + (size_t)R * HDIM + col);
        float vv[4] = {v.x, v.y, v.z, v.w};
        ushort4 w4;
        unsigned short* wp = &w4.x;
#pragma unroll
        for (int j = 0; j < 4; j++)
            wp[j] = __half_as_ushort(__float2half_rn(vv[j]));
        *(ushort4*)(g_WL + (size_t)R * HDIM + col) = w4;
    } else {
        // activations: A (ci-perm) + E (cat-perm)
        const int p = bid - (MCI * GDIM + KCAT * CCH);
        {
            const int t = g_perm_ci[p];
#pragma unroll
            for (int r = 0; r < 3; r++) {
                int col = (tid + 128 * r) * 4;
                float4 v = (col < INDIM)
                         ? *(const float4*)(x + (size_t)t * INDIM + col)
                         : *(const float4*)(h + (size_t)t * HDIM + (col - INDIM));
                float vv[4] = {v.x, v.y, v.z, v.w};
                ushort4 a4;
                unsigned short* ap = &a4.x;
#pragma unroll
                for (int j = 0; j < 4; j++)
                    ap[j] = __half_as_ushort(__float2half_rn(vv[j]));
                *(ushort4*)(g_A + (size_t)p * FDIM + col) = a4;
            }
        }
        {
            const int t = g_perm_cat[p];
            int col = tid * 4;
            float4 v = *(const float4*)(et + (size_t)t * HDIM + col);
            float vv[4] = {v.x, v.y, v.z, v.w};
            ushort4 e4;
            unsigned short* ep4 = &e4.x;
#pragma unroll
            for (int j = 0; j < 4; j++)
                ep4[j] = __half_as_ushort(__float2half_rn(vv[j]));
            *(ushort4*)(g_E + (size_t)p * HDIM + col) = e4;
        }
    }
}

// ---------------- stage loaders ----------------
__device__ __forceinline__ void load_stage(int tid, uint32_t sb, int b,
                                           int arow0, int brow0, int ccol) {
#pragma unroll
    for (int i = 0; i < 8; i++) {
        int cidx = tid + 256 * i;        // 0..2047
        int mat  = cidx >> 10;           // 0=A 1=B
        int cc   = cidx & 1023;
        int row  = cc >> 3;
        int c16  = cc & 7;
        uint32_t dst = sb + SM_STG + b * STGB + mat * MATB + row * ROWB + c16 * 16;
        const __half* src = (mat == 0)
            ? g_A + (size_t)(arow0 + row) * FDIM + ccol + c16 * 8
            : g_W + (size_t)(brow0 + row) * FDIM + ccol + c16 * 8;
        cpa16(dst, src);
    }
    CP_COMMIT();
}

__device__ __forceinline__ void load_stage_lo(int tid, uint32_t sb, int b,
                                              int erow0, int wrow0, int ccol) {
#pragma unroll
    for (int i = 0; i < 6; i++) {
        int cidx = tid + 256 * i;        // 0..1535
        uint32_t base = sb + SM_STG + b * LSTG;
        if (cidx < 512) {
            int row = cidx >> 3, c16 = cidx & 7;
            cpa16(base + row * ROWB + c16 * 16,
                  g_E + (size_t)(erow0 + row) * HDIM + ccol + c16 * 8);
        } else {
            int cc = cidx - 512;         // 0..1023
            int row = cc >> 3, c16 = cc & 7;
            cpa16(base + LMATE + row * ROWB + c16 * 16,
                  g_WL + (size_t)(wrow0 + row) * HDIM + ccol + c16 * 8);
        }
    }
    CP_COMMIT();
}

// ---------------- fused MMA kernel: gates (z=0..3) + logodds (z=4) ----------------
__global__ __launch_bounds__(256, 2) void fused_mma(
    const float* __restrict__ c_in,
    const float* __restrict__ b_ih, const float* __restrict__ b_hh,
    const float* __restrict__ b_lin,
    float* __restrict__ out)
{
    extern __shared__ char smem[];
    const uint32_t sb = smem_u32(smem);
    const int tid = threadIdx.x;
    const int w   = tid >> 5;
    const int l   = tid & 31;
    const int lr   = l & 15;
    const int lc16 = (l >> 4) << 4;

    if (blockIdx.z < MCI) {
        // ================= GATES =================
        const int k   = blockIdx.z;
        const int beg = g_off_ci[k];
        const int cnt = g_off_ci[k + 1] - beg;
        const int m0  = blockIdx.x * BM;
        if (m0 >= cnt) return;
        const int n0  = blockIdx.y * BN;
        const int wm  = w >> 2;
        const int wn  = w & 3;

        if (tid < 128) {
            int j = n0 + tid;
            int u = j >> 2, gate = j & 3;
            int g = gate * 512 + u;
            ((float*)(smem + SM_BIAS))[tid] = b_ih[k * GDIM + g] + b_hh[k * GDIM + g];
        }

        const int arow0 = beg + m0;
        const int brow0 = k * GDIM + n0;

        float acc[4][4][4];
#pragma unroll
        for (int a = 0; a < 4; a++)
#pragma unroll
            for (int b2 = 0; b2 < 4; b2++)
#pragma unroll
                for (int c = 0; c < 4; c++) acc[a][b2][c] = 0.f;

        load_stage(tid, sb, 0, arow0, brow0, 0);
        load_stage(tid, sb, 1, arow0, brow0, BK);
        load_stage(tid, sb, 2, arow0, brow0, 2 * BK);

        int b = 0;
        for (int s = 0; s < NSTAGES; s++) {
            if (s <= NSTAGES - 3)      cp_wait<2>();
            else if (s == NSTAGES - 2) cp_wait<1>();
            else                       cp_wait<0>();
            __syncthreads();

            const uint32_t stg = sb + SM_STG + b * STGB;
            const uint32_t aA = stg, bB = stg + MATB;

#pragma unroll
            for (int ks = 0; ks < 4; ks++) {
                const int kb = ks * 32 + lc16;
                uint32_t bb[2][4], af[4][4];
#pragma unroll
                for (int g2 = 0; g2 < 2; g2++) {
                    uint32_t brow = wn * 32 + g2 * 16 + lr;
                    ldm4(bb[g2], bB + brow * ROWB + kb);
                }
#pragma unroll
                for (int mi = 0; mi < 4; mi++) {
                    uint32_t arow = wm * 64 + mi * 16 + lr;
                    ldm4(af[mi], aA + arow * ROWB + kb);
                }
#pragma unroll
                for (int mi = 0; mi < 4; mi++)
#pragma unroll
                    for (int ni = 0; ni < 4; ni++)
                        mma16816(acc[mi][ni], af[mi], bb[ni >> 1][ni & 1], bb[ni >> 1][(ni & 1) + 2]);
            }

            __syncthreads();
            if (s + 3 < NSTAGES) load_stage(tid, sb, b, arow0, brow0, (s + 3) * BK);
            b = (b == NBUF - 1) ? 0 : b + 1;
        }

        // epilogue: acc -> smem f32 tile -> fused LSTM
        float* ep = (float*)(smem + SM_STG);
#pragma unroll
        for (int mi = 0; mi < 4; mi++)
#pragma unroll
            for (int ni = 0; ni < 4; ni++) {
                int r0 = wm * 64 + mi * 16 + (l >> 2);
                int c0 = wn * 32 + ni * 8 + (l & 3) * 2;
                *(float2*)&ep[r0 * EPW + c0]       = make_float2(acc[mi][ni][0], acc[mi][ni][1]);
                *(float2*)&ep[(r0 + 8) * EPW + c0] = make_float2(acc[mi][ni][2], acc[mi][ni][3]);
            }
        __syncthreads();

        const float* bias = (const float*)(smem + SM_BIAS);
        const int row = tid >> 1;
        const int uu0 = (tid & 1) * 16;
        const int m = m0 + row;
        if (m < cnt) {
            const int t  = g_perm_ci[beg + m];
            const int u0 = n0 >> 2;
            const size_t OFF_H = (size_t)NTOK * CCH;
            const size_t OFF_C = OFF_H + (size_t)NTOK * HDIM;
#pragma unroll
            for (int j = 0; j < 16; j++) {
                int uu = uu0 + j;
                float4 v = *(const float4*)&ep[row * EPW + uu * 4];
                float iv = v.x + bias[4 * uu + 0];
                float fv = v.y + bias[4 * uu + 1];
                float gv = v.z + bias[4 * uu + 2];
                float ov = v.w + bias[4 * uu + 3];
                int u = u0 + uu;
                float cold = c_in[(size_t)t * HDIM + u];
                float si = 1.f / (1.f + expf(-iv));
                float sf = 1.f / (1.f + expf(-fv));
                float so = 1.f / (1.f + expf(-ov));
                float c2 = sf * cold + si * tanhf(gv);
                float h2 = so * tanhf(c2);
                out[OFF_H + (size_t)t * HDIM + u] = h2;
                out[OFF_C + (size_t)t * HDIM + u] = c2;
            }
        }
    } else {
        // ================= LOGODDS =================
        const int flat = blockIdx.x * 16 + blockIdx.y;
        if (flat >= 3 * KCAT) return;
        const int kc = flat / 3;
        const int mt = flat - kc * 3;
        const int beg = g_off_cat[kc];
        const int cnt = g_off_cat[kc + 1] - beg;
        const int m0  = mt * LBM;
        if (m0 >= cnt) return;
        const int wm  = w >> 2;        // 0..1 (32 rows each)
        const int wn  = w & 3;         // 0..3 (32 cols each)

        if (tid < CCH)
            ((float*)(smem + SM_BIAS))[tid] = b_lin[kc * CCH + tid];

        const int erow0 = beg + m0;
        const int wrow0 = kc * CCH;

        float acc[2][4][4];
#pragma unroll
        for (int a = 0; a < 2; a++)
#pragma unroll
            for (int b2 = 0; b2 < 4; b2++)
#pragma unroll
                for (int c = 0; c < 4; c++) acc[a][b2][c] = 0.f;

        load_stage_lo(tid, sb, 0, erow0, wrow0, 0);
        load_stage_lo(tid, sb, 1, erow0, wrow0, LBK);
        load_stage_lo(tid, sb, 2, erow0, wrow0, 2 * LBK);

        int b = 0;
        for (int s = 0; s < LNST; s++) {
            if (s <= LNST - 3)      cp_wait<2>();
            else if (s == LNST - 2) cp_wait<1>();
            else                    cp_wait<0>();
            __syncthreads();

            const uint32_t stg = sb + SM_STG + b * LSTG;
            const uint32_t eE = stg, wB = stg + LMATE;

#pragma unroll
            for (int ks = 0; ks < 4; ks++) {
                const int kb = ks * 32 + lc16;
                uint32_t bb[2][4], af[2][4];
#pragma unroll
                for (int g2 = 0; g2 < 2; g2++) {
                    uint32_t brow = wn * 32 + g2 * 16 + lr;
                    ldm4(bb[g2], wB + brow * ROWB + kb);
                }
#pragma unroll
                for (int mi = 0; mi < 2; mi++) {
                    uint32_t arow = wm * 32 + mi * 16 + lr;
                    ldm4(af[mi], eE + arow * ROWB + kb);
                }
#pragma unroll
                for (int mi = 0; mi < 2; mi++)
#pragma unroll
                    for (int ni = 0; ni < 4; ni++)
                        mma16816(acc[mi][ni], af[mi], bb[ni >> 1][ni & 1], bb[ni >> 1][(ni & 1) + 2]);
            }

            __syncthreads();
            if (s + 3 < LNST) load_stage_lo(tid, sb, b, erow0, wrow0, (s + 3) * LBK);
            b = (b == NBUF - 1) ? 0 : b + 1;
        }

        const float* bias = (const float*)(smem + SM_BIAS);
#pragma unroll
        for (int mi = 0; mi < 2; mi++) {
            int r1 = wm * 32 + mi * 16 + (l >> 2);
            int r2 = r1 + 8;
            int m1 = m0 + r1, m2 = m0 + r2;
            int t1 = (m1 < cnt) ? g_perm_cat[beg + m1] : -1;
            int t2 = (m2 < cnt) ? g_perm_cat[beg + m2] : -1;
#pragma unroll
            for (int ni = 0; ni < 4; ni++) {
                int c0 = wn * 32 + ni * 8 + (l & 3) * 2;
                float b0 = bias[c0], b1 = bias[c0 + 1];
                if (t1 >= 0)
                    *(float2*)(out + (size_t)t1 * CCH + c0)
                        = make_float2(acc[mi][ni][0] + b0, acc[mi][ni][1] + b1);
                if (t2 >= 0)
                    *(float2*)(out + (size_t)t2 * CCH + c0)
                        = make_float2(acc[mi][ni][2] + b0, acc[mi][ni][3] + b1);
            }
        }
    }
}

// ---------------- launch ----------------
extern "C" void kernel_launch(void* const* d_in, const int* in_sizes, int n_in,
                              void* d_out, int out_size) {
    const float* et    = (const float*)d_in[0];
    const float* x     = (const float*)d_in[1];
    const float* h     = (const float*)d_in[2];
    const float* c     = (const float*)d_in[3];
    const int*   cat   = (const int*)d_in[4];
    const int*   ci    = (const int*)d_in[5];
    const float* W_lin = (const float*)d_in[6];
    const float* b_lin = (const float*)d_in[7];
    const float* W_ih  = (const float*)d_in[8];
    const float* W_hh  = (const float*)d_in[9];
    const float* b_ih  = (const float*)d_in[10];
    const float* b_hh  = (const float*)d_in[11];
    float* out = (float*)d_out;

    cudaFuncSetAttribute(fused_mma, cudaFuncAttributeMaxDynamicSharedMemorySize, SM_TOTAL);

    k_sort<<<1, 1024>>>(cat, ci);

    pack_all<<<MCI * GDIM + KCAT * CCH + NTOK, 128>>>(W_ih, W_hh, W_lin, x, h, et);

    fused_mma<<<dim3(NTOK / BM, GDIM / BN, MCI + 1), 256, SM_TOTAL>>>(
        c, b_ih, b_hh, b_lin, out);
}

// round 17
// speedup vs baseline: 5.8539x; 1.0415x over previous
#include <cuda_runtime.h>
#include <cuda_fp16.h>
#include <math.h>
#include <stdint.h>

// Problem constants
#define NTOK  4096
#define HDIM  512
#define CCH   128
#define KCAT  64
#define MCI   4
#define INDIM 1024
#define GDIM  2048      // 4*H
#define FDIM  1536      // INDIM + HDIM

// gates GEMM tiling
#define BM 128
#define BN 128
#define BK 64
#define NSTAGES (FDIM / BK)     // 24
#define NBUF 3
#define ROWB 144                // 64 fp16 = 128B data + 16B pad
#define MATB (BM * ROWB)        // 18432
#define STGB (2 * MATB)         // 36864
#define SM_IDX  0               // 128 ints (row -> token)
#define SM_BIAS 512
#define SM_STG  1024
#define EPW 136                 // epilogue f32 row stride (floats)
#define SM_TOTAL (SM_STG + NBUF * STGB)   // 111616

// logodds tiling (single-pass fp16, LBK=64, 3-buf) — fits inside SM_TOTAL
#define LBM 64
#define LBK 64
#define LNST (HDIM / LBK)       // 8
#define LMATE (LBM * ROWB)      // 9216
#define LMATW (CCH * ROWB)      // 18432
#define LSTG  (LMATE + LMATW)   // 27648

// ---------------- device scratch (static) ----------------
__device__ __half g_A[(size_t)NTOK * FDIM];    // token order
__device__ __half g_W[(size_t)MCI * GDIM * FDIM];
__device__ __half g_E[(size_t)NTOK * HDIM];    // token order
__device__ __half g_WL[(size_t)KCAT * CCH * HDIM];
__device__ int g_perm_ci[NTOK];
__device__ int g_perm_cat[NTOK];
__device__ int g_off_ci[MCI + 1];
__device__ int g_off_cat[KCAT + 1];

// ---------------- PTX helpers (sm_80-level only) ----------------
__device__ __forceinline__ uint32_t smem_u32(const void* p) {
    uint32_t a;
    asm("{ .reg .u64 t; cvta.to.shared.u64 t, %1; cvt.u32.u64 %0, t; }" : "=r"(a) : "l"(p));
    return a;
}
__device__ __forceinline__ void cpa16(uint32_t dst, const void* src) {
    asm volatile("cp.async.cg.shared.global [%0], [%1], 16;" :: "r"(dst), "l"(src));
}
#define CP_COMMIT() asm volatile("cp.async.commit_group;" ::: "memory")
template <int N> __device__ __forceinline__ void cp_wait() {
    asm volatile("cp.async.wait_group %0;" :: "n"(N) : "memory");
}
__device__ __forceinline__ void ldm4(uint32_t* r, uint32_t addr) {
    asm volatile("ldmatrix.sync.aligned.m8n8.x4.shared.b16 {%0,%1,%2,%3}, [%4];"
        : "=r"(r[0]), "=r"(r[1]), "=r"(r[2]), "=r"(r[3]) : "r"(addr));
}
__device__ __forceinline__ void mma16816(float* c, const uint32_t* a, uint32_t b0, uint32_t b1) {
    asm volatile(
        "mma.sync.aligned.m16n8k16.row.col.f32.f16.f16.f32 "
        "{%0,%1,%2,%3}, {%4,%5,%6,%7}, {%8,%9}, {%0,%1,%2,%3};"
        : "+f"(c[0]), "+f"(c[1]), "+f"(c[2]), "+f"(c[3])
        : "r"(a[0]), "r"(a[1]), "r"(a[2]), "r"(a[3]), "r"(b0), "r"(b1));
}

// ---------------- merged pack + sort kernel ----------------
// bid 0: counting sort (1 block). bid 1..: weight + activation packs (sort-independent).
__global__ __launch_bounds__(128) void pack_sort(const int* __restrict__ cat,
                                                 const int* __restrict__ ci,
                                                 const float* __restrict__ W_ih,
                                                 const float* __restrict__ W_hh,
                                                 const float* __restrict__ W_lin,
                                                 const float* __restrict__ x,
                                                 const float* __restrict__ h,
                                                 const float* __restrict__ et) {
    const int tid = threadIdx.x;
    const int bid = blockIdx.x;

    if (bid == 0) {
        // ---- counting sort (independent of all pack blocks) ----
        __shared__ int s_ci[MCI], s_cat[KCAT], p_ci[MCI], p_cat[KCAT];
        if (tid < MCI)  s_ci[tid]  = 0;
        if (tid < KCAT) s_cat[tid] = 0;
        __syncthreads();
        for (int n = tid; n < NTOK; n += 128) {
            atomicAdd(&s_ci[ci[n]], 1);
            atomicAdd(&s_cat[cat[n]], 1);
        }
        __syncthreads();
        if (tid == 0) {
            int s = 0;
            for (int i = 0; i < MCI; i++) { g_off_ci[i] = s; p_ci[i] = s; s += s_ci[i]; }
            g_off_ci[MCI] = s;
        }
        if (tid == 32) {
            int s = 0;
            for (int i = 0; i < KCAT; i++) { g_off_cat[i] = s; p_cat[i] = s; s += s_cat[i]; }
            g_off_cat[KCAT] = s;
        }
        __syncthreads();
        for (int n = tid; n < NTOK; n += 128) {
            g_perm_ci[atomicAdd(&p_ci[ci[n]], 1)] = n;
            g_perm_cat[atomicAdd(&p_cat[cat[n]], 1)] = n;
        }
        return;
    }

    const int wb = bid - 1;
    if (wb < MCI * GDIM) {
        // gates weights, i-f-g-o interleaved rows
        const int R = wb;
        const int k = R >> 11;
        const int r = R & 2047;
        const int u = r >> 2;
        const int gate = r & 3;
        const int g = gate * 512 + u;
        const float* src_ih = W_ih + ((size_t)k * GDIM + g) * INDIM;
        const float* src_hh = W_hh + ((size_t)k * GDIM + g) * HDIM;
#pragma unroll
        for (int rr = 0; rr < 3; rr++) {
            int col = (tid + 128 * rr) * 4;
            float4 v = (col < INDIM) ? *(const float4*)(src_ih + col)
                                     : *(const float4*)(src_hh + (col - INDIM));
            float vv[4] = {v.x, v.y, v.z, v.w};
            ushort4 w4;
            unsigned short* wp = &w4.x;
#pragma unroll
            for (int j = 0; j < 4; j++)
                wp[j] = __half_as_ushort(__float2half_rn(vv[j]));
            *(ushort4*)(g_W + (size_t)R * FDIM + col) = w4;
        }
    } else if (wb < MCI * GDIM + KCAT * CCH) {
        const int R = wb - MCI * GDIM;
        int col = tid * 4;
        float4 v = *(const float4*)(W_lin + (size_t)R * HDIM + col);
        float vv[4] = {v.x, v.y, v.z, v.w};
        ushort4 w4;
        unsigned short* wp = &w4.x;
#pragma unroll
        for (int j = 0; j < 4; j++)
            wp[j] = __half_as_ushort(__float2half_rn(vv[j]));
        *(ushort4*)(g_WL + (size_t)R * HDIM + col) = w4;
    } else {
        // activations in TOKEN order (no perm dependency)
        const int p = wb - (MCI * GDIM + KCAT * CCH);
#pragma unroll
        for (int r = 0; r < 3; r++) {
            int col = (tid + 128 * r) * 4;
            float4 v = (col < INDIM)
                     ? *(const float4*)(x + (size_t)p * INDIM + col)
                     : *(const float4*)(h + (size_t)p * HDIM + (col - INDIM));
            float vv[4] = {v.x, v.y, v.z, v.w};
            ushort4 a4;
            unsigned short* ap = &a4.x;
#pragma unroll
            for (int j = 0; j < 4; j++)
                ap[j] = __half_as_ushort(__float2half_rn(vv[j]));
            *(ushort4*)(g_A + (size_t)p * FDIM + col) = a4;
        }
        {
            int col = tid * 4;
            float4 v = *(const float4*)(et + (size_t)p * HDIM + col);
            float vv[4] = {v.x, v.y, v.z, v.w};
            ushort4 e4;
            unsigned short* ep4 = &e4.x;
#pragma unroll
            for (int j = 0; j < 4; j++)
                ep4[j] = __half_as_ushort(__float2half_rn(vv[j]));
            *(ushort4*)(g_E + (size_t)p * HDIM + col) = e4;
        }
    }
}

// ---------------- stage loaders (A/E gathered via smem row-index cache) ----------------
__device__ __forceinline__ void load_stage(int tid, uint32_t sb, const int* sidx, int b,
                                           int brow0, int ccol) {
#pragma unroll
    for (int i = 0; i < 8; i++) {
        int cidx = tid + 256 * i;        // 0..2047
        int mat  = cidx >> 10;           // 0=A 1=B
        int cc   = cidx & 1023;
        int row  = cc >> 3;
        int c16  = cc & 7;
        uint32_t dst = sb + SM_STG + b * STGB + mat * MATB + row * ROWB + c16 * 16;
        const __half* src = (mat == 0)
            ? g_A + (size_t)sidx[row] * FDIM + ccol + c16 * 8
            : g_W + (size_t)(brow0 + row) * FDIM + ccol + c16 * 8;
        cpa16(dst, src);
    }
    CP_COMMIT();
}

__device__ __forceinline__ void load_stage_lo(int tid, uint32_t sb, const int* sidx, int b,
                                              int wrow0, int ccol) {
#pragma unroll
    for (int i = 0; i < 6; i++) {
        int cidx = tid + 256 * i;        // 0..1535
        uint32_t base = sb + SM_STG + b * LSTG;
        if (cidx < 512) {
            int row = cidx >> 3, c16 = cidx & 7;
            cpa16(base + row * ROWB + c16 * 16,
                  g_E + (size_t)sidx[row] * HDIM + ccol + c16 * 8);
        } else {
            int cc = cidx - 512;         // 0..1023
            int row = cc >> 3, c16 = cc & 7;
            cpa16(base + LMATE + row * ROWB + c16 * 16,
                  g_WL + (size_t)(wrow0 + row) * HDIM + ccol + c16 * 8);
        }
    }
    CP_COMMIT();
}

// ---------------- fused MMA kernel: gates (z=0..3) + logodds (z=4) ----------------
__global__ __launch_bounds__(256, 2) void fused_mma(
    const float* __restrict__ c_in,
    const float* __restrict__ b_ih, const float* __restrict__ b_hh,
    const float* __restrict__ b_lin,
    float* __restrict__ out)
{
    extern __shared__ char smem[];
    const uint32_t sb = smem_u32(smem);
    int* sidx = (int*)(smem + SM_IDX);
    const int tid = threadIdx.x;
    const int w   = tid >> 5;
    const int l   = tid & 31;
    const int lr   = l & 15;
    const int lc16 = (l >> 4) << 4;

    if (blockIdx.z < MCI) {
        // ================= GATES =================
        const int k   = blockIdx.z;
        const int beg = g_off_ci[k];
        const int cnt = g_off_ci[k + 1] - beg;
        const int m0  = blockIdx.x * BM;
        if (m0 >= cnt) return;
        const int n0  = blockIdx.y * BN;
        const int wm  = w >> 2;
        const int wn  = w & 3;

        if (tid < 128) {
            int p = beg + m0 + tid;
            sidx[tid] = (p < NTOK) ? g_perm_ci[p] : 0;
            int j = n0 + tid;
            int u = j >> 2, gate = j & 3;
            int g = gate * 512 + u;
            ((float*)(smem + SM_BIAS))[tid] = b_ih[k * GDIM + g] + b_hh[k * GDIM + g];
        }
        __syncthreads();

        const int brow0 = k * GDIM + n0;

        float acc[4][4][4];
#pragma unroll
        for (int a = 0; a < 4; a++)
#pragma unroll
            for (int b2 = 0; b2 < 4; b2++)
#pragma unroll
                for (int c = 0; c < 4; c++) acc[a][b2][c] = 0.f;

        load_stage(tid, sb, sidx, 0, brow0, 0);
        load_stage(tid, sb, sidx, 1, brow0, BK);
        load_stage(tid, sb, sidx, 2, brow0, 2 * BK);

        int b = 0;
        for (int s = 0; s < NSTAGES; s++) {
            if (s <= NSTAGES - 3)      cp_wait<2>();
            else if (s == NSTAGES - 2) cp_wait<1>();
            else                       cp_wait<0>();
            __syncthreads();

            const uint32_t stg = sb + SM_STG + b * STGB;
            const uint32_t aA = stg, bB = stg + MATB;

#pragma unroll
            for (int ks = 0; ks < 4; ks++) {
                const int kb = ks * 32 + lc16;
                uint32_t bb[2][4], af[4][4];
#pragma unroll
                for (int g2 = 0; g2 < 2; g2++) {
                    uint32_t brow = wn * 32 + g2 * 16 + lr;
                    ldm4(bb[g2], bB + brow * ROWB + kb);
                }
#pragma unroll
                for (int mi = 0; mi < 4; mi++) {
                    uint32_t arow = wm * 64 + mi * 16 + lr;
                    ldm4(af[mi], aA + arow * ROWB + kb);
                }
#pragma unroll
                for (int mi = 0; mi < 4; mi++)
#pragma unroll
                    for (int ni = 0; ni < 4; ni++)
                        mma16816(acc[mi][ni], af[mi], bb[ni >> 1][ni & 1], bb[ni >> 1][(ni & 1) + 2]);
            }

            __syncthreads();
            if (s + 3 < NSTAGES) load_stage(tid, sb, sidx, b, brow0, (s + 3) * BK);
            b = (b == NBUF - 1) ? 0 : b + 1;
        }

        // epilogue: acc -> smem f32 tile -> fused LSTM
        float* ep = (float*)(smem + SM_STG);
#pragma unroll
        for (int mi = 0; mi < 4; mi++)
#pragma unroll
            for (int ni = 0; ni < 4; ni++) {
                int r0 = wm * 64 + mi * 16 + (l >> 2);
                int c0 = wn * 32 + ni * 8 + (l & 3) * 2;
                *(float2*)&ep[r0 * EPW + c0]       = make_float2(acc[mi][ni][0], acc[mi][ni][1]);
                *(float2*)&ep[(r0 + 8) * EPW + c0] = make_float2(acc[mi][ni][2], acc[mi][ni][3]);
            }
        __syncthreads();

        const float* bias = (const float*)(smem + SM_BIAS);
        const int row = tid >> 1;
        const int uu0 = (tid & 1) * 16;
        const int m = m0 + row;
        if (m < cnt) {
            const int t  = sidx[row];
            const int u0 = n0 >> 2;
            const size_t OFF_H = (size_t)NTOK * CCH;
            const size_t OFF_C = OFF_H + (size_t)NTOK * HDIM;
#pragma unroll
            for (int j = 0; j < 16; j++) {
                int uu = uu0 + j;
                float4 v = *(const float4*)&ep[row * EPW + uu * 4];
                float iv = v.x + bias[4 * uu + 0];
                float fv = v.y + bias[4 * uu + 1];
                float gv = v.z + bias[4 * uu + 2];
                float ov = v.w + bias[4 * uu + 3];
                int u = u0 + uu;
                float cold = c_in[(size_t)t * HDIM + u];
                float si = 1.f / (1.f + expf(-iv));
                float sf = 1.f / (1.f + expf(-fv));
                float so = 1.f / (1.f + expf(-ov));
                float c2 = sf * cold + si * tanhf(gv);
                float h2 = so * tanhf(c2);
                out[OFF_H + (size_t)t * HDIM + u] = h2;
                out[OFF_C + (size_t)t * HDIM + u] = c2;
            }
        }
    } else {
        // ================= LOGODDS =================
        const int flat = blockIdx.x * 16 + blockIdx.y;
        if (flat >= 3 * KCAT) return;
        const int kc = flat / 3;
        const int mt = flat - kc * 3;
        const int beg = g_off_cat[kc];
        const int cnt = g_off_cat[kc + 1] - beg;
        const int m0  = mt * LBM;
        if (m0 >= cnt) return;
        const int wm  = w >> 2;
        const int wn  = w & 3;

        if (tid < 128) {
            if (tid < LBM) {
                int p = beg + m0 + tid;
                sidx[tid] = (p < NTOK) ? g_perm_cat[p] : 0;
            }
            ((float*)(smem + SM_BIAS))[tid] = b_lin[kc * CCH + tid];
        }
        __syncthreads();

        const int wrow0 = kc * CCH;

        float acc[2][4][4];
#pragma unroll
        for (int a = 0; a < 2; a++)
#pragma unroll
            for (int b2 = 0; b2 < 4; b2++)
#pragma unroll
                for (int c = 0; c < 4; c++) acc[a][b2][c] = 0.f;

        load_stage_lo(tid, sb, sidx, 0, wrow0, 0);
        load_stage_lo(tid, sb, sidx, 1, wrow0, LBK);
        load_stage_lo(tid, sb, sidx, 2, wrow0, 2 * LBK);

        int b = 0;
        for (int s = 0; s < LNST; s++) {
            if (s <= LNST - 3)      cp_wait<2>();
            else if (s == LNST - 2) cp_wait<1>();
            else                    cp_wait<0>();
            __syncthreads();

            const uint32_t stg = sb + SM_STG + b * LSTG;
            const uint32_t eE = stg, wB = stg + LMATE;

#pragma unroll
            for (int ks = 0; ks < 4; ks++) {
                const int kb = ks * 32 + lc16;
                uint32_t bb[2][4], af[2][4];
#pragma unroll
                for (int g2 = 0; g2 < 2; g2++) {
                    uint32_t brow = wn * 32 + g2 * 16 + lr;
                    ldm4(bb[g2], wB + brow * ROWB + kb);
                }
#pragma unroll
                for (int mi = 0; mi < 2; mi++) {
                    uint32_t arow = wm * 32 + mi * 16 + lr;
                    ldm4(af[mi], eE + arow * ROWB + kb);
                }
#pragma unroll
                for (int mi = 0; mi < 2; mi++)
#pragma unroll
                    for (int ni = 0; ni < 4; ni++)
                        mma16816(acc[mi][ni], af[mi], bb[ni >> 1][ni & 1], bb[ni >> 1][(ni & 1) + 2]);
            }

            __syncthreads();
            if (s + 3 < LNST) load_stage_lo(tid, sb, sidx, b, wrow0, (s + 3) * LBK);
            b = (b == NBUF - 1) ? 0 : b + 1;
        }

        const float* bias = (const float*)(smem + SM_BIAS);
#pragma unroll
        for (int mi = 0; mi < 2; mi++) {
            int r1 = wm * 32 + mi * 16 + (l >> 2);
            int r2 = r1 + 8;
            int m1 = m0 + r1, m2 = m0 + r2;
            int t1 = (m1 < cnt) ? sidx[r1] : -1;
            int t2 = (m2 < cnt) ? sidx[r2] : -1;
#pragma unroll
            for (int ni = 0; ni < 4; ni++) {
                int c0 = wn * 32 + ni * 8 + (l & 3) * 2;
                float b0 = bias[c0], b1 = bias[c0 + 1];
                if (t1 >= 0)
                    *(float2*)(out + (size_t)t1 * CCH + c0)
                        = make_float2(acc[mi][ni][0] + b0, acc[mi][ni][1] + b1);
                if (t2 >= 0)
                    *(float2*)(out + (size_t)t2 * CCH + c0)
                        = make_float2(acc[mi][ni][2] + b0, acc[mi][ni][3] + b1);
            }
        }
    }
}

// ---------------- launch ----------------
extern "C" void kernel_launch(void* const* d_in, const int* in_sizes, int n_in,
                              void* d_out, int out_size) {
    const float* et    = (const float*)d_in[0];
    const float* x     = (const float*)d_in[1];
    const float* h     = (const float*)d_in[2];
    const float* c     = (const float*)d_in[3];
    const int*   cat   = (const int*)d_in[4];
    const int*   ci    = (const int*)d_in[5];
    const float* W_lin = (const float*)d_in[6];
    const float* b_lin = (const float*)d_in[7];
    const float* W_ih  = (const float*)d_in[8];
    const float* W_hh  = (const float*)d_in[9];
    const float* b_ih  = (const float*)d_in[10];
    const float* b_hh  = (const float*)d_in[11];
    float* out = (float*)d_out;

    cudaFuncSetAttribute(fused_mma, cudaFuncAttributeMaxDynamicSharedMemorySize, SM_TOTAL);

    pack_sort<<<1 + MCI * GDIM + KCAT * CCH + NTOK, 128>>>(
        cat, ci, W_ih, W_hh, W_lin, x, h, et);

    fused_mma<<<dim3(NTOK / BM, GDIM / BN, MCI + 1), 256, SM_TOTAL>>>(
        c, b_ih, b_hh, b_lin, out);
}